// round 1
// baseline (speedup 1.0000x reference)
#include <cuda_runtime.h>
#include <cuda_bf16.h>

#define Bdim 32
#define Tdim 128
#define Zdim 100
#define Sdim 6
#define Hdim 64
#define F1 512
#define F2 128
#define ZB (Zdim * Bdim)          // 3200
#define NROWS (ZB * Tdim)         // 409600

// ---------------- device scratch (no allocation allowed) ----------------
__device__ float g_sx[ZB * Tdim * Hdim];   // GRU outputs, row-major [row][64]
__device__ float g_w1d[Hdim * 2 * F1];     // w1 transposed + duplicated: [k][2c],[k][2c+1] = w1[c][k]
__device__ float g_w2d[F1 * 2 * F2];       // w2 transposed + duplicated
__device__ float g_w3d[2 * F2];            // w3 duplicated

// ---------------- packed fp32 helpers (sm_103a f32x2 pipe) ----------------
__device__ __forceinline__ void ffma2(unsigned long long &d, unsigned long long a, unsigned long long b) {
    asm("fma.rn.f32x2 %0, %1, %2, %0;" : "+l"(d) : "l"(a), "l"(b));
}
__device__ __forceinline__ void add2(unsigned long long &d, unsigned long long a) {
    asm("add.rn.f32x2 %0, %0, %1;" : "+l"(d) : "l"(a));
}
__device__ __forceinline__ unsigned long long packdup(float v) {
    unsigned long long r; asm("mov.b64 %0, {%1, %1};" : "=l"(r) : "f"(v)); return r;
}
__device__ __forceinline__ unsigned long long pack2(float lo, float hi) {
    unsigned long long r; asm("mov.b64 %0, {%1, %2};" : "=l"(r) : "f"(lo), "f"(hi)); return r;
}
__device__ __forceinline__ float2 unpack2(unsigned long long v) {
    float2 r; asm("mov.b64 {%0, %1}, %2;" : "=f"(r.x), "=f"(r.y) : "l"(v)); return r;
}

__device__ __forceinline__ float sigmoidf_(float v) {
    return 1.0f / (1.0f + expf(-v));
}

// ---------------- weight prep: transpose + duplicate ----------------
__global__ void prep_kernel(const float* __restrict__ w1,
                            const float* __restrict__ w2,
                            const float* __restrict__ w3) {
    int i = blockIdx.x * blockDim.x + threadIdx.x;
    if (i < Hdim * F1) {                       // 32768
        int k = i >> 9, c = i & 511;           // k<64, c<512
        float v = w1[c * Hdim + k];
        g_w1d[k * (2 * F1) + 2 * c]     = v;
        g_w1d[k * (2 * F1) + 2 * c + 1] = v;
    }
    if (i < F1 * F2) {                         // 65536
        int k = i >> 7, c = i & 127;           // k<512, c<128
        float v = w2[c * F1 + k];
        g_w2d[k * (2 * F2) + 2 * c]     = v;
        g_w2d[k * (2 * F2) + 2 * c + 1] = v;
    }
    if (i < F2) {
        float v = w3[i];
        g_w3d[2 * i]     = v;
        g_w3d[2 * i + 1] = v;
    }
}

// ---------------- GRU kernel ----------------
// 192 threads = one gate row each (3H = 192). 8 sequences per block.
// h kept in shared, W_hh row in registers (packed f32x2).
#define NSEQ 8
__global__ __launch_bounds__(192) void gru_kernel(
    const float* __restrict__ x,
    const float* __restrict__ Wih,
    const float* __restrict__ Whh,
    const float* __restrict__ bih,
    const float* __restrict__ bhh)
{
    __shared__ __align__(16) float h_sh[NSEQ][Hdim];
    __shared__ float r_sh[NSEQ][Hdim];
    __shared__ float z_sh[NSEQ][Hdim];
    __shared__ float xs[NSEQ][Sdim];

    const int g = threadIdx.x;            // 0..191 gate row
    const int n0 = blockIdx.x * NSEQ;     // base sequence, same zone for all 8
    const int zz = n0 >> 5;               // n = zz*B + bb, NSEQ=8 divides B=32
    const int bb0 = n0 & 31;

    float wih[Sdim];
#pragma unroll
    for (int s = 0; s < Sdim; s++) wih[s] = Wih[g * Sdim + s];

    unsigned long long whh2[Hdim / 2];
    {
        const float2* wrow = (const float2*)(Whh + g * Hdim);
#pragma unroll
        for (int i = 0; i < Hdim / 2; i++) {
            float2 w = wrow[i];
            whh2[i] = pack2(w.x, w.y);
        }
    }
    const float bi = bih[g];
    const float bh = bhh[g];

    for (int i = g; i < NSEQ * Hdim; i += 192) ((float*)h_sh)[i] = 0.0f;
    __syncthreads();

    const int j = g - 128;   // >=0 for the "n" gate threads (they also do h update)

    for (int t = 0; t < Tdim; t++) {
        if (g < NSEQ * Sdim) {
            int q = g / Sdim, s = g % Sdim;
            xs[q][s] = x[(((bb0 + q) * Tdim + t) * Zdim + zz) * Sdim + s];
        }
        __syncthreads();

        float gi[NSEQ], gh[NSEQ];
#pragma unroll
        for (int q = 0; q < NSEQ; q++) {
            float a = bi;
#pragma unroll
            for (int s = 0; s < Sdim; s++) a = fmaf(wih[s], xs[q][s], a);
            gi[q] = a;

            unsigned long long acc = 0ull;   // {0.0f, 0.0f}
            const unsigned long long* hp = (const unsigned long long*)h_sh[q];
#pragma unroll
            for (int i = 0; i < Hdim / 2; i++) ffma2(acc, whh2[i], hp[i]);
            float2 hv = unpack2(acc);
            gh[q] = bh + hv.x + hv.y;
        }

        if (g < 64) {
#pragma unroll
            for (int q = 0; q < NSEQ; q++) r_sh[q][g] = sigmoidf_(gi[q] + gh[q]);
        } else if (g < 128) {
#pragma unroll
            for (int q = 0; q < NSEQ; q++) z_sh[q][g - 64] = sigmoidf_(gi[q] + gh[q]);
        }
        __syncthreads();

        if (j >= 0) {
#pragma unroll
            for (int q = 0; q < NSEQ; q++) {
                float nn = tanhf(gi[q] + r_sh[q][j] * gh[q]);
                float zg = z_sh[q][j];
                float hn = nn + zg * (h_sh[q][j] - nn);
                h_sh[q][j] = hn;
                g_sx[(((n0 + q) * Tdim) + t) * Hdim + j] = hn;
            }
        }
        __syncthreads();
    }
}

// ---------------- fused MLP kernel ----------------
// One warp processes 8 consecutive rows. a1 tile staged in shared per warp.
// All GEMM math in packed f32x2: accumulators packed over row-pairs,
// weights pre-duplicated so LDG.128 yields {w[c],w[c],w[c+1],w[c+1]}.
#define MLP_SM_PER_WARP (Hdim * 10 + F1 * 10)   // xT[64][10] + a1T[512][10] floats

__global__ __launch_bounds__(256, 1) void mlp_kernel(
    const float* __restrict__ b1,
    const float* __restrict__ b2,
    const float* __restrict__ b3,
    float* __restrict__ out)
{
    extern __shared__ float smbuf[];
    const int wid = threadIdx.x >> 5;
    const int l   = threadIdx.x & 31;
    float* xT  = smbuf + wid * MLP_SM_PER_WARP;  // [64][10] transposed x rows
    float* a1T = xT + Hdim * 10;                 // [512][10]

    const int row0 = (blockIdx.x * 8 + wid) * 8;   // 8 rows per warp

    // ---- stage 8 rows of sx, transposed: xT[k][r] ----
#pragma unroll
    for (int jj = 0; jj < 16; jj++) {
        int idx = l + 32 * jj;                     // 0..511, coalesced
        float v = g_sx[row0 * Hdim + idx];
        xT[(idx & 63) * 10 + (idx >> 6)] = v;
    }
    __syncwarp();

    // ---- layer 1: 64 -> 512, relu, store to a1T ----
#pragma unroll
    for (int ch = 0; ch < 2; ch++) {
        unsigned long long A[4][2][4];
#pragma unroll
        for (int jj = 0; jj < 4; jj++) {
            int c0 = 2 * (ch * 128 + l + 32 * jj);
            unsigned long long d0 = packdup(b1[c0]);
            unsigned long long d1 = packdup(b1[c0 + 1]);
#pragma unroll
            for (int rp = 0; rp < 4; rp++) { A[jj][0][rp] = d0; A[jj][1][rp] = d1; }
        }
#pragma unroll 4
        for (int k = 0; k < Hdim; k++) {
            unsigned long long xp0 = *(const unsigned long long*)&xT[k * 10 + 0];
            unsigned long long xp1 = *(const unsigned long long*)&xT[k * 10 + 2];
            unsigned long long xp2 = *(const unsigned long long*)&xT[k * 10 + 4];
            unsigned long long xp3 = *(const unsigned long long*)&xT[k * 10 + 6];
#pragma unroll
            for (int jj = 0; jj < 4; jj++) {
                ulonglong2 wv = *(const ulonglong2*)&g_w1d[k * (2 * F1) + 4 * (ch * 128 + l + 32 * jj)];
                ffma2(A[jj][0][0], wv.x, xp0); ffma2(A[jj][0][1], wv.x, xp1);
                ffma2(A[jj][0][2], wv.x, xp2); ffma2(A[jj][0][3], wv.x, xp3);
                ffma2(A[jj][1][0], wv.y, xp0); ffma2(A[jj][1][1], wv.y, xp1);
                ffma2(A[jj][1][2], wv.y, xp2); ffma2(A[jj][1][3], wv.y, xp3);
            }
        }
#pragma unroll
        for (int jj = 0; jj < 4; jj++) {
            int c0 = 2 * (ch * 128 + l + 32 * jj);
#pragma unroll
            for (int cc = 0; cc < 2; cc++) {
#pragma unroll
                for (int rp = 0; rp < 4; rp++) {
                    float2 v = unpack2(A[jj][cc][rp]);
                    v.x = fmaxf(v.x, 0.0f);
                    v.y = fmaxf(v.y, 0.0f);
                    *(float2*)&a1T[(c0 + cc) * 10 + 2 * rp] = v;
                }
            }
        }
    }
    __syncwarp();

    // ---- layer 2: 512 -> 128 ----
    unsigned long long A2[2][2][4];
#pragma unroll
    for (int jj = 0; jj < 2; jj++) {
        int c0 = 2 * (l + 32 * jj);
        unsigned long long d0 = packdup(b2[c0]);
        unsigned long long d1 = packdup(b2[c0 + 1]);
#pragma unroll
        for (int rp = 0; rp < 4; rp++) { A2[jj][0][rp] = d0; A2[jj][1][rp] = d1; }
    }
#pragma unroll 4
    for (int k = 0; k < F1; k++) {
        unsigned long long xp0 = *(const unsigned long long*)&a1T[k * 10 + 0];
        unsigned long long xp1 = *(const unsigned long long*)&a1T[k * 10 + 2];
        unsigned long long xp2 = *(const unsigned long long*)&a1T[k * 10 + 4];
        unsigned long long xp3 = *(const unsigned long long*)&a1T[k * 10 + 6];
#pragma unroll
        for (int jj = 0; jj < 2; jj++) {
            ulonglong2 wv = *(const ulonglong2*)&g_w2d[k * (2 * F2) + 4 * (l + 32 * jj)];
            ffma2(A2[jj][0][0], wv.x, xp0); ffma2(A2[jj][0][1], wv.x, xp1);
            ffma2(A2[jj][0][2], wv.x, xp2); ffma2(A2[jj][0][3], wv.x, xp3);
            ffma2(A2[jj][1][0], wv.y, xp0); ffma2(A2[jj][1][1], wv.y, xp1);
            ffma2(A2[jj][1][2], wv.y, xp2); ffma2(A2[jj][1][3], wv.y, xp3);
        }
    }
    // relu (packed, stays packed for layer 3)
#pragma unroll
    for (int jj = 0; jj < 2; jj++)
#pragma unroll
        for (int cc = 0; cc < 2; cc++)
#pragma unroll
            for (int rp = 0; rp < 4; rp++) {
                float2 v = unpack2(A2[jj][cc][rp]);
                A2[jj][cc][rp] = pack2(fmaxf(v.x, 0.0f), fmaxf(v.y, 0.0f));
            }

    // ---- layer 3: 128 -> 1 (warp reduction) ----
    unsigned long long acc3[4] = {0ull, 0ull, 0ull, 0ull};
#pragma unroll
    for (int jj = 0; jj < 2; jj++) {
        ulonglong2 wv = *(const ulonglong2*)&g_w3d[4 * (l + 32 * jj)];
#pragma unroll
        for (int rp = 0; rp < 4; rp++) {
            ffma2(acc3[rp], wv.x, A2[jj][0][rp]);
            ffma2(acc3[rp], wv.y, A2[jj][1][rp]);
        }
    }
#pragma unroll
    for (int s = 0; s < 5; s++) {
        int off = 16 >> s;
#pragma unroll
        for (int rp = 0; rp < 4; rp++) {
            unsigned long long o = __shfl_xor_sync(0xffffffffu, acc3[rp], off);
            add2(acc3[rp], o);
        }
    }
    if (l == 0) {
        float bb = *b3;
#pragma unroll
        for (int rp = 0; rp < 4; rp++) {
            float2 v = unpack2(acc3[rp]);
            out[row0 + 2 * rp]     = v.x + bb;
            out[row0 + 2 * rp + 1] = v.y + bb;
        }
    }
}

// ---------------- launch ----------------
extern "C" void kernel_launch(void* const* d_in, const int* in_sizes, int n_in,
                              void* d_out, int out_size) {
    const float* x    = (const float*)d_in[0];
    const float* W_ih = (const float*)d_in[1];
    const float* W_hh = (const float*)d_in[2];
    const float* b_ih = (const float*)d_in[3];
    const float* b_hh = (const float*)d_in[4];
    const float* w1   = (const float*)d_in[5];
    const float* b1   = (const float*)d_in[6];
    const float* w2   = (const float*)d_in[7];
    const float* b2   = (const float*)d_in[8];
    const float* w3   = (const float*)d_in[9];
    const float* b3   = (const float*)d_in[10];
    float* out = (float*)d_out;

    // weight prep (transpose + duplicate); 65536 threads covers all tables
    prep_kernel<<<256, 256>>>(w1, w2, w3);

    // GRU: 3200 sequences / 8 per block
    gru_kernel<<<ZB / NSEQ, 192>>>(x, W_ih, W_hh, b_ih, b_hh);

    // MLP: 409600 rows / (8 warps * 8 rows) per block
    static const size_t mlp_smem = 8 * MLP_SM_PER_WARP * sizeof(float); // 184320 B
    cudaFuncSetAttribute(mlp_kernel, cudaFuncAttributeMaxDynamicSharedMemorySize, (int)mlp_smem);
    mlp_kernel<<<NROWS / 64, 256, mlp_smem>>>(b1, b2, b3, out);
}

// round 2
// speedup vs baseline: 1.1588x; 1.1588x over previous
#include <cuda_runtime.h>
#include <cuda_bf16.h>

#define Bdim 32
#define Tdim 128
#define Zdim 100
#define Sdim 6
#define Hdim 64
#define F1 512
#define F2 128
#define ZB (Zdim * Bdim)          // 3200
#define NROWS (ZB * Tdim)         // 409600

// ---------------- device scratch ----------------
__device__ float g_sx[ZB * Tdim * Hdim];       // GRU outputs [row][64]
// w1 transposed, chunk-major: g_w1t[ch][k][128] with c = ch*128 + cl
__device__ float g_w1t[Hdim * F1];
// w2 transposed: g_w2t[k][128]
__device__ float g_w2t[F1 * F2];

// ---------------- packed fp32 helpers ----------------
__device__ __forceinline__ void ffma2(unsigned long long &d, unsigned long long a, unsigned long long b) {
    asm("fma.rn.f32x2 %0, %1, %2, %0;" : "+l"(d) : "l"(a), "l"(b));
}
__device__ __forceinline__ void add2(unsigned long long &d, unsigned long long a) {
    asm("add.rn.f32x2 %0, %0, %1;" : "+l"(d) : "l"(a));
}
__device__ __forceinline__ unsigned long long packdup(float v) {
    unsigned long long r; asm("mov.b64 %0, {%1, %1};" : "=l"(r) : "f"(v)); return r;
}
__device__ __forceinline__ unsigned long long pack2(float lo, float hi) {
    unsigned long long r; asm("mov.b64 %0, {%1, %2};" : "=l"(r) : "f"(lo), "f"(hi)); return r;
}
__device__ __forceinline__ float2 unpack2(unsigned long long v) {
    float2 r; asm("mov.b64 {%0, %1}, %2;" : "=f"(r.x), "=f"(r.y) : "l"(v)); return r;
}
__device__ __forceinline__ float sigmoidf_(float v) {
    return 1.0f / (1.0f + expf(-v));
}

// ---------------- weight prep: transpose ----------------
__global__ void prep_kernel(const float* __restrict__ w1,
                            const float* __restrict__ w2) {
    int i = blockIdx.x * blockDim.x + threadIdx.x;
    if (i < Hdim * F1) {                    // 32768: w1t[ch][k][cl] = w1[c][k]
        int ch = i >> 13;                   // /(64*128)
        int k  = (i >> 7) & 63;
        int cl = i & 127;
        int c  = ch * 128 + cl;
        g_w1t[i] = w1[c * Hdim + k];
    }
    if (i < F1 * F2) {                      // 65536: w2t[k][c] = w2[c][k]
        int k = i >> 7, c = i & 127;
        g_w2t[i] = w2[c * F1 + k];
    }
}

// ---------------- GRU kernel ----------------
#define NSEQ 8
__global__ __launch_bounds__(192) void gru_kernel(
    const float* __restrict__ x,
    const float* __restrict__ Wih,
    const float* __restrict__ Whh,
    const float* __restrict__ bih,
    const float* __restrict__ bhh)
{
    __shared__ __align__(16) float h_sh[NSEQ][Hdim];
    __shared__ float r_sh[NSEQ][Hdim];
    __shared__ float z_sh[NSEQ][Hdim];
    __shared__ float xs[NSEQ][Sdim];

    const int g = threadIdx.x;            // 0..191 gate row
    const int n0 = blockIdx.x * NSEQ;
    const int zz = n0 >> 5;
    const int bb0 = n0 & 31;

    float wih[Sdim];
#pragma unroll
    for (int s = 0; s < Sdim; s++) wih[s] = Wih[g * Sdim + s];

    unsigned long long whh2[Hdim / 2];
    {
        const float2* wrow = (const float2*)(Whh + g * Hdim);
#pragma unroll
        for (int i = 0; i < Hdim / 2; i++) {
            float2 w = wrow[i];
            whh2[i] = pack2(w.x, w.y);
        }
    }
    const float bi = bih[g];
    const float bh = bhh[g];

    for (int i = g; i < NSEQ * Hdim; i += 192) ((float*)h_sh)[i] = 0.0f;
    __syncthreads();

    const int j = g - 128;

    for (int t = 0; t < Tdim; t++) {
        if (g < NSEQ * Sdim) {
            int q = g / Sdim, s = g % Sdim;
            xs[q][s] = x[(((bb0 + q) * Tdim + t) * Zdim + zz) * Sdim + s];
        }
        __syncthreads();

        float gi[NSEQ], gh[NSEQ];
#pragma unroll
        for (int q = 0; q < NSEQ; q++) {
            float a = bi;
#pragma unroll
            for (int s = 0; s < Sdim; s++) a = fmaf(wih[s], xs[q][s], a);
            gi[q] = a;

            unsigned long long acc = 0ull;
            const ulonglong2* hp = (const ulonglong2*)h_sh[q];
#pragma unroll
            for (int i = 0; i < Hdim / 4; i++) {
                ulonglong2 hv = hp[i];
                ffma2(acc, whh2[2 * i], hv.x);
                ffma2(acc, whh2[2 * i + 1], hv.y);
            }
            float2 hv = unpack2(acc);
            gh[q] = bh + hv.x + hv.y;
        }

        if (g < 64) {
#pragma unroll
            for (int q = 0; q < NSEQ; q++) r_sh[q][g] = sigmoidf_(gi[q] + gh[q]);
        } else if (g < 128) {
#pragma unroll
            for (int q = 0; q < NSEQ; q++) z_sh[q][g - 64] = sigmoidf_(gi[q] + gh[q]);
        }
        __syncthreads();

        if (j >= 0) {
#pragma unroll
            for (int q = 0; q < NSEQ; q++) {
                float nn = tanhf(gi[q] + r_sh[q][j] * gh[q]);
                float zg = z_sh[q][j];
                float hn = nn + zg * (h_sh[q][j] - nn);
                h_sh[q][j] = hn;
                g_sx[(((n0 + q) * Tdim) + t) * Hdim + j] = hn;
            }
        }
        __syncthreads();
    }
}

// ---------------- fused MLP kernel v2 ----------------
// Block: 4 warps x 16 rows = 64 rows. Weights staged undup'd in a 32KB shared
// buffer shared by all warps, duplicated into f32x2 at use via one MOV.
// Accumulators: 4 cols/lane x 8 row-pairs, packed over rows.
#define MWARPS 4
#define RPW 16                    // rows per warp
#define XSTRIDE 18                // floats per k-row in xT/a1T (bank-friendly, 8B-aligned)
#define A1T_FLOATS (F1 * XSTRIDE)       // 9216 per warp
#define XT_FLOATS  (Hdim * XSTRIDE)     // 1152 per warp
#define WBUF_FLOATS 8192                // 32KB staging chunk

__global__ __launch_bounds__(128, 1) void mlp_kernel(
    const float* __restrict__ b1,
    const float* __restrict__ b2,
    const float* __restrict__ b3,
    const float* __restrict__ w3,
    float* __restrict__ out)
{
    extern __shared__ float smbuf[];
    float* a1base = smbuf;                                  // 4 * 9216
    float* xbase  = a1base + MWARPS * A1T_FLOATS;           // 4 * 1152
    float* wbuf   = xbase + MWARPS * XT_FLOATS;             // 8192

    const int tid = threadIdx.x;
    const int wid = tid >> 5;
    const int l   = tid & 31;
    float* a1T = a1base + wid * A1T_FLOATS;
    float* xT  = xbase  + wid * XT_FLOATS;

    const int row0 = (blockIdx.x * MWARPS + wid) * RPW;

    // ---- stage 16 rows of sx, transposed: xT[k][r], r packed pairs ----
#pragma unroll
    for (int jj = 0; jj < 32; jj++) {
        int idx = l + 32 * jj;                 // 0..1023
        float v = g_sx[row0 * Hdim + idx];
        xT[(idx & 63) * XSTRIDE + (idx >> 6)] = v;
    }
    __syncwarp();

    // ---- layer 1: 64 -> 512 in 4 col-chunks of 128 ----
#pragma unroll 1
    for (int ch = 0; ch < 4; ch++) {
        __syncthreads();
        // stage w1T chunk: contiguous 8192 floats
        {
            const float4* src = (const float4*)(g_w1t + ch * WBUF_FLOATS);
            float4* dst = (float4*)wbuf;
            for (int i = tid; i < WBUF_FLOATS / 4; i += 128) dst[i] = src[i];
        }
        __syncthreads();

        unsigned long long A[4][8];
        {
            float4 bb = *(const float4*)&b1[ch * 128 + l * 4];
            unsigned long long d0 = packdup(bb.x), d1 = packdup(bb.y);
            unsigned long long d2 = packdup(bb.z), d3 = packdup(bb.w);
#pragma unroll
            for (int p = 0; p < 8; p++) { A[0][p] = d0; A[1][p] = d1; A[2][p] = d2; A[3][p] = d3; }
        }
#pragma unroll 8
        for (int k = 0; k < Hdim; k++) {
            float4 wv = *(const float4*)&wbuf[k * 128 + l * 4];
            unsigned long long w0 = packdup(wv.x), w1_ = packdup(wv.y);
            unsigned long long w2_ = packdup(wv.z), w3_ = packdup(wv.w);
            unsigned long long xp[8];
#pragma unroll
            for (int p = 0; p < 8; p++) xp[p] = *(const unsigned long long*)&xT[k * XSTRIDE + 2 * p];
#pragma unroll
            for (int p = 0; p < 8; p++) {
                ffma2(A[0][p], w0, xp[p]);
                ffma2(A[1][p], w1_, xp[p]);
                ffma2(A[2][p], w2_, xp[p]);
                ffma2(A[3][p], w3_, xp[p]);
            }
        }
        // relu + store to a1T
#pragma unroll
        for (int cc = 0; cc < 4; cc++) {
            int c = ch * 128 + l * 4 + cc;
#pragma unroll
            for (int p = 0; p < 8; p++) {
                float2 v = unpack2(A[cc][p]);
                v.x = fmaxf(v.x, 0.0f);
                v.y = fmaxf(v.y, 0.0f);
                *(float2*)&a1T[c * XSTRIDE + 2 * p] = v;
            }
        }
    }

    // ---- layer 2: 512 -> 128 in 8 k-chunks of 64 ----
    unsigned long long A2[4][8];
    {
        float4 bb = *(const float4*)&b2[l * 4];
        unsigned long long d0 = packdup(bb.x), d1 = packdup(bb.y);
        unsigned long long d2 = packdup(bb.z), d3 = packdup(bb.w);
#pragma unroll
        for (int p = 0; p < 8; p++) { A2[0][p] = d0; A2[1][p] = d1; A2[2][p] = d2; A2[3][p] = d3; }
    }
#pragma unroll 1
    for (int kc = 0; kc < 8; kc++) {
        __syncthreads();
        {
            const float4* src = (const float4*)(g_w2t + kc * WBUF_FLOATS);
            float4* dst = (float4*)wbuf;
            for (int i = tid; i < WBUF_FLOATS / 4; i += 128) dst[i] = src[i];
        }
        __syncthreads();
#pragma unroll 8
        for (int k = 0; k < 64; k++) {
            float4 wv = *(const float4*)&wbuf[k * 128 + l * 4];
            unsigned long long w0 = packdup(wv.x), w1_ = packdup(wv.y);
            unsigned long long w2_ = packdup(wv.z), w3_ = packdup(wv.w);
            int kg = kc * 64 + k;
            unsigned long long xp[8];
#pragma unroll
            for (int p = 0; p < 8; p++) xp[p] = *(const unsigned long long*)&a1T[kg * XSTRIDE + 2 * p];
#pragma unroll
            for (int p = 0; p < 8; p++) {
                ffma2(A2[0][p], w0, xp[p]);
                ffma2(A2[1][p], w1_, xp[p]);
                ffma2(A2[2][p], w2_, xp[p]);
                ffma2(A2[3][p], w3_, xp[p]);
            }
        }
    }

    // relu on A2 (packed)
#pragma unroll
    for (int cc = 0; cc < 4; cc++)
#pragma unroll
        for (int p = 0; p < 8; p++) {
            float2 v = unpack2(A2[cc][p]);
            A2[cc][p] = pack2(fmaxf(v.x, 0.0f), fmaxf(v.y, 0.0f));
        }

    // ---- layer 3: 128 -> 1 ----
    unsigned long long acc3[8];
    {
        float4 wv = *(const float4*)&w3[l * 4];
        unsigned long long w0 = packdup(wv.x), w1_ = packdup(wv.y);
        unsigned long long w2_ = packdup(wv.z), w3_ = packdup(wv.w);
#pragma unroll
        for (int p = 0; p < 8; p++) {
            unsigned long long a = 0ull;
            ffma2(a, w0, A2[0][p]);
            ffma2(a, w1_, A2[1][p]);
            ffma2(a, w2_, A2[2][p]);
            ffma2(a, w3_, A2[3][p]);
            acc3[p] = a;
        }
    }
#pragma unroll
    for (int s = 0; s < 5; s++) {
        int off = 16 >> s;
#pragma unroll
        for (int p = 0; p < 8; p++) {
            unsigned long long o = __shfl_xor_sync(0xffffffffu, acc3[p], off);
            add2(acc3[p], o);
        }
    }
    if (l == 0) {
        float bb = *b3;
#pragma unroll
        for (int p = 0; p < 8; p++) {
            float2 v = unpack2(acc3[p]);
            out[row0 + 2 * p]     = v.x + bb;
            out[row0 + 2 * p + 1] = v.y + bb;
        }
    }
}

// ---------------- launch ----------------
extern "C" void kernel_launch(void* const* d_in, const int* in_sizes, int n_in,
                              void* d_out, int out_size) {
    const float* x    = (const float*)d_in[0];
    const float* W_ih = (const float*)d_in[1];
    const float* W_hh = (const float*)d_in[2];
    const float* b_ih = (const float*)d_in[3];
    const float* b_hh = (const float*)d_in[4];
    const float* w1   = (const float*)d_in[5];
    const float* b1   = (const float*)d_in[6];
    const float* w2   = (const float*)d_in[7];
    const float* b2   = (const float*)d_in[8];
    const float* w3   = (const float*)d_in[9];
    const float* b3   = (const float*)d_in[10];
    float* out = (float*)d_out;

    prep_kernel<<<256, 256>>>(w1, w2);

    gru_kernel<<<ZB / NSEQ, 192>>>(x, W_ih, W_hh, b_ih, b_hh);

    const size_t mlp_smem =
        (MWARPS * (A1T_FLOATS + XT_FLOATS) + WBUF_FLOATS) * sizeof(float); // 198656 B
    static int attr_set = 0;
    if (!attr_set) {
        cudaFuncSetAttribute(mlp_kernel, cudaFuncAttributeMaxDynamicSharedMemorySize, (int)mlp_smem);
        attr_set = 1;
    }
    mlp_kernel<<<NROWS / (MWARPS * RPW), 128, mlp_smem>>>(b1, b2, b3, w3, out);
}

// round 4
// speedup vs baseline: 2.0635x; 1.7808x over previous
#include <cuda_runtime.h>
#include <cuda_bf16.h>
#include <cstdint>

#define Bdim 32
#define Tdim 128
#define Zdim 100
#define Sdim 6
#define Hdim 64
#define F1 512
#define F2 128
#define ZB (Zdim * Bdim)          // 3200 sequences = 3200 MLP tiles of 128 rows
#define NROWS (ZB * Tdim)         // 409600

// ---------------- device scratch ----------------
// GRU outputs, bf16 hi/lo, plain row-major A tiles: tile n rows t=0..127, cols k=0..63
__device__ __align__(16) __nv_bfloat16 g_ahi[NROWS * Hdim];
__device__ __align__(16) __nv_bfloat16 g_alo[NROWS * Hdim];
// w1 [512][64] bf16 hi/lo (plain row-major); w2 [128][512] hi/lo
__device__ __align__(16) __nv_bfloat16 g_b1hi[F1 * Hdim];
__device__ __align__(16) __nv_bfloat16 g_b1lo[F1 * Hdim];
__device__ __align__(16) __nv_bfloat16 g_b2hi[F2 * F1];
__device__ __align__(16) __nv_bfloat16 g_b2lo[F2 * F1];

// ---------------- packed fp32 helpers (GRU) ----------------
__device__ __forceinline__ void ffma2(unsigned long long &d, unsigned long long a, unsigned long long b) {
    asm("fma.rn.f32x2 %0, %1, %2, %0;" : "+l"(d) : "l"(a), "l"(b));
}
__device__ __forceinline__ unsigned long long pack2(float lo, float hi) {
    unsigned long long r; asm("mov.b64 %0, {%1, %2};" : "=l"(r) : "f"(lo), "f"(hi)); return r;
}
__device__ __forceinline__ float2 unpack2(unsigned long long v) {
    float2 r; asm("mov.b64 {%0, %1}, %2;" : "=f"(r.x), "=f"(r.y) : "l"(v)); return r;
}
__device__ __forceinline__ float sigmoidf_(float v) { return 1.0f / (1.0f + expf(-v)); }

// ---------------- mma / ldmatrix helpers (sm_80+ ISA, legal on sm_103) ----------------
__device__ __forceinline__ uint32_t smem_u32(const void* p) {
    uint32_t a;
    asm("{ .reg .u64 t; cvta.to.shared.u64 t, %1; cvt.u32.u64 %0, t; }" : "=r"(a) : "l"(p));
    return a;
}
__device__ __forceinline__ void ldsm_x4(uint32_t* r, uint32_t addr) {
    asm volatile("ldmatrix.sync.aligned.m8n8.x4.shared.b16 {%0,%1,%2,%3}, [%4];"
                 : "=r"(r[0]), "=r"(r[1]), "=r"(r[2]), "=r"(r[3]) : "r"(addr));
}
__device__ __forceinline__ void ldsm_x2(uint32_t* r, uint32_t addr) {
    asm volatile("ldmatrix.sync.aligned.m8n8.x2.shared.b16 {%0,%1}, [%2];"
                 : "=r"(r[0]), "=r"(r[1]) : "r"(addr));
}
__device__ __forceinline__ void mma_bf16(float* d, const uint32_t* a, const uint32_t* b) {
    asm volatile("mma.sync.aligned.m16n8k16.row.col.f32.bf16.bf16.f32 "
                 "{%0,%1,%2,%3}, {%4,%5,%6,%7}, {%8,%9}, {%0,%1,%2,%3};"
                 : "+f"(d[0]), "+f"(d[1]), "+f"(d[2]), "+f"(d[3])
                 : "r"(a[0]), "r"(a[1]), "r"(a[2]), "r"(a[3]), "r"(b[0]), "r"(b[1]));
}
__device__ __forceinline__ uint32_t bfpack(float x, float y) {
    __nv_bfloat162 t = __floats2bfloat162_rn(x, y);
    return *(uint32_t*)&t;
}

// ---------------- weight prep: bf16 split (plain layout) ----------------
__global__ void prep_kernel(const float* __restrict__ w1,
                            const float* __restrict__ w2) {
    int i = blockIdx.x * blockDim.x + threadIdx.x;
    if (i < F1 * Hdim) {
        float v = w1[i];
        __nv_bfloat16 h = __float2bfloat16(v);
        g_b1hi[i] = h;
        g_b1lo[i] = __float2bfloat16(v - __bfloat162float(h));
    }
    if (i < F2 * F1) {
        float v = w2[i];
        __nv_bfloat16 h = __float2bfloat16(v);
        g_b2hi[i] = h;
        g_b2lo[i] = __float2bfloat16(v - __bfloat162float(h));
    }
}

// ---------------- GRU kernel ----------------
#define NSEQ 8
__global__ __launch_bounds__(192) void gru_kernel(
    const float* __restrict__ x,
    const float* __restrict__ Wih,
    const float* __restrict__ Whh,
    const float* __restrict__ bih,
    const float* __restrict__ bhh)
{
    __shared__ __align__(16) float h_sh[NSEQ][Hdim];
    __shared__ float r_sh[NSEQ][Hdim];
    __shared__ float z_sh[NSEQ][Hdim];
    __shared__ float xs[NSEQ][Sdim];

    const int g = threadIdx.x;
    const int n0 = blockIdx.x * NSEQ;
    const int zz = n0 >> 5;
    const int bb0 = n0 & 31;

    float wih[Sdim];
#pragma unroll
    for (int s = 0; s < Sdim; s++) wih[s] = Wih[g * Sdim + s];

    unsigned long long whh2[Hdim / 2];
    {
        const float2* wrow = (const float2*)(Whh + g * Hdim);
#pragma unroll
        for (int i = 0; i < Hdim / 2; i++) { float2 w = wrow[i]; whh2[i] = pack2(w.x, w.y); }
    }
    const float bi = bih[g];
    const float bh = bhh[g];

    for (int i = g; i < NSEQ * Hdim; i += 192) ((float*)h_sh)[i] = 0.0f;
    __syncthreads();

    const int j = g - 128;

    for (int t = 0; t < Tdim; t++) {
        if (g < NSEQ * Sdim) {
            int q = g / Sdim, s = g % Sdim;
            xs[q][s] = x[(((bb0 + q) * Tdim + t) * Zdim + zz) * Sdim + s];
        }
        __syncthreads();

        float gi[NSEQ], gh[NSEQ];
#pragma unroll
        for (int q = 0; q < NSEQ; q++) {
            float a = bi;
#pragma unroll
            for (int s = 0; s < Sdim; s++) a = fmaf(wih[s], xs[q][s], a);
            gi[q] = a;

            unsigned long long acc = 0ull;
            const ulonglong2* hp = (const ulonglong2*)h_sh[q];
#pragma unroll
            for (int i = 0; i < Hdim / 4; i++) {
                ulonglong2 hv = hp[i];
                ffma2(acc, whh2[2 * i], hv.x);
                ffma2(acc, whh2[2 * i + 1], hv.y);
            }
            float2 hv = unpack2(acc);
            gh[q] = bh + hv.x + hv.y;
        }

        if (g < 64) {
#pragma unroll
            for (int q = 0; q < NSEQ; q++) r_sh[q][g] = sigmoidf_(gi[q] + gh[q]);
        } else if (g < 128) {
#pragma unroll
            for (int q = 0; q < NSEQ; q++) z_sh[q][g - 64] = sigmoidf_(gi[q] + gh[q]);
        }
        __syncthreads();

        if (j >= 0) {
#pragma unroll
            for (int q = 0; q < NSEQ; q++) {
                float nn = tanhf(gi[q] + r_sh[q][j] * gh[q]);
                float zg = z_sh[q][j];
                float hn = nn + zg * (h_sh[q][j] - nn);
                h_sh[q][j] = hn;
                __nv_bfloat16 hi = __float2bfloat16(hn);
                int idx = (n0 + q) * (Tdim * Hdim) + t * Hdim + j;
                g_ahi[idx] = hi;
                g_alo[idx] = __float2bfloat16(hn - __bfloat162float(hi));
            }
        }
        __syncthreads();
    }
}

// ---------------- tensor-core fused MLP (mma.sync bf16, split hi/lo) ----------------
// CTA = one sequence tile (M=128), 8 warps x 16 rows. Fused 64->512(relu)->128(relu)->1.
// Layer-1 D fragments feed layer-2 A fragments directly in registers.
#define SA1 72      // b16 stride of A1 smem rows (144B: conflict-free ldmatrix)
#define SW1 72
#define SW2 136     // 272B
#define OFF_A1HI 0
#define OFF_A1LO 18432
#define OFF_W1HI 36864
#define OFF_W1LO 55296
#define OFF_W2HI 73728
#define OFF_W2LO 108544
#define OFF_B1   143360
#define OFF_B2   145408
#define OFF_W3   145920
#define SM_TOTAL 146432

__global__ __launch_bounds__(256, 1) void mlp_kernel(
    const float* __restrict__ b1,
    const float* __restrict__ b2,
    const float* __restrict__ b3,
    const float* __restrict__ w3,
    float* __restrict__ out)
{
    extern __shared__ char sm[];
    const int tid = threadIdx.x;
    const int w = tid >> 5;
    const int lane = tid & 31;
    const int qp = lane & 3;        // quad position (n/k pair index)
    const int qr = lane >> 2;       // quad row (m within 8)
    const int bid = blockIdx.x;

    float* b1s = (float*)(sm + OFF_B1);
    float* b2s = (float*)(sm + OFF_B2);
    float* w3s = (float*)(sm + OFF_W3);
    for (int i = tid; i < F1; i += 256) b1s[i] = b1[i];
    if (tid < F2) { b2s[tid] = b2[tid]; w3s[tid] = w3[tid]; }

    // ---- stage A1 tile (hi/lo), rows stride SA1 ----
    {
        const uint4* shp = (const uint4*)(g_ahi + (size_t)bid * (Tdim * Hdim));
        const uint4* slp = (const uint4*)(g_alo + (size_t)bid * (Tdim * Hdim));
        for (int i = tid; i < 1024; i += 256) {
            int r = i >> 3, c = i & 7;
            *(uint4*)(sm + OFF_A1HI + r * (SA1 * 2) + c * 16) = shp[i];
            *(uint4*)(sm + OFF_A1LO + r * (SA1 * 2) + c * 16) = slp[i];
        }
    }
    __syncthreads();

    // ---- per-lane ldmatrix addresses ----
    // A-frag (x4): mats: {m0..7,k0..7},{m8..15,k0..7},{m0..7,k8..15},{m8..15,k8..15}
    const int arow = w * 16 + ((lane >> 3) & 1) * 8 + (lane & 7);
    const int acol = ((lane >> 4) & 1) * 8;
    const uint32_t uA1hi = smem_u32(sm + OFF_A1HI) + (arow * SA1 + acol) * 2;
    const uint32_t uA1lo = smem_u32(sm + OFF_A1LO) + (arow * SA1 + acol) * 2;
    // B-frag (x2): lanes 0-7 rows of {n0..7,k0..7}, lanes 8-15 rows of {n0..7,k8..15}
    const int Lb = lane & 15;
    const int brow = Lb & 7;
    const int bkof = (Lb >> 3) * 8;
    const uint32_t uW1hi = smem_u32(sm + OFF_W1HI) + (brow * SW1 + bkof) * 2;
    const uint32_t uW1lo = smem_u32(sm + OFF_W1LO) + (brow * SW1 + bkof) * 2;
    const uint32_t uW2hi = smem_u32(sm + OFF_W2HI) + (brow * SW2 + bkof) * 2;
    const uint32_t uW2lo = smem_u32(sm + OFF_W2LO) + (brow * SW2 + bkof) * 2;

    // ---- load A1 fragments once (4 k-steps, hi+lo) ----
    uint32_t Ah[4][4], Al[4][4];
#pragma unroll
    for (int kk = 0; kk < 4; kk++) {
        ldsm_x4(Ah[kk], uA1hi + kk * 32);
        ldsm_x4(Al[kk], uA1lo + kk * 32);
    }

    float D2[16][4];
#pragma unroll
    for (int j = 0; j < 16; j++)
#pragma unroll
        for (int p = 0; p < 4; p++) D2[j][p] = 0.0f;

    for (int ch = 0; ch < 4; ch++) {
        __syncthreads();   // protect W buffers from previous iteration's readers
        // stage W1 chunk [128][64] hi/lo
        {
            const uint4* s0 = (const uint4*)(g_b1hi + ch * 128 * Hdim);
            const uint4* s1 = (const uint4*)(g_b1lo + ch * 128 * Hdim);
            for (int i = tid; i < 1024; i += 256) {
                int r = i >> 3, c = i & 7;
                *(uint4*)(sm + OFF_W1HI + r * (SW1 * 2) + c * 16) = s0[i];
                *(uint4*)(sm + OFF_W1LO + r * (SW1 * 2) + c * 16) = s1[i];
            }
        }
        // stage W2 chunk [128][128] hi/lo (k-slice ch*128)
        {
            for (int i = tid; i < 2048; i += 256) {
                int r = i >> 4, c = i & 15;
                *(uint4*)(sm + OFF_W2HI + r * (SW2 * 2) + c * 16) =
                    *(const uint4*)(g_b2hi + r * F1 + ch * 128 + c * 8);
                *(uint4*)(sm + OFF_W2LO + r * (SW2 * 2) + c * 16) =
                    *(const uint4*)(g_b2lo + r * F1 + ch * 128 + c * 8);
            }
        }
        __syncthreads();

#pragma unroll 1
        for (int s = 0; s < 8; s++) {
            // ---- layer1: two n-tiles (n = ch*128 + (2s+jj)*8 ...) ----
            float D1[2][4];
#pragma unroll
            for (int jj = 0; jj < 2; jj++) {
#pragma unroll
                for (int p = 0; p < 4; p++) D1[jj][p] = 0.0f;
                const int j = 2 * s + jj;
                const uint32_t bh_base = uW1hi + j * 8 * SW1 * 2;
                const uint32_t bl_base = uW1lo + j * 8 * SW1 * 2;
#pragma unroll
                for (int kk = 0; kk < 4; kk++) {
                    uint32_t bh[2], bl[2];
                    ldsm_x2(bh, bh_base + kk * 32);
                    ldsm_x2(bl, bl_base + kk * 32);
                    mma_bf16(D1[jj], Ah[kk], bh);
                    mma_bf16(D1[jj], Ah[kk], bl);
                    mma_bf16(D1[jj], Al[kk], bh);
                }
            }
            // ---- epilogue: relu(D1+b1) -> split bf16 -> layer2 A fragments ----
            uint32_t ah[4], al[4];
#pragma unroll
            for (int jj = 0; jj < 2; jj++) {
                const int nb = ch * 128 + (2 * s + jj) * 8 + 2 * qp;
                const float bb0 = b1s[nb], bb1 = b1s[nb + 1];
#pragma unroll
                for (int pp = 0; pp < 2; pp++) {
                    float v0 = fmaxf(D1[jj][2 * pp] + bb0, 0.0f);
                    float v1 = fmaxf(D1[jj][2 * pp + 1] + bb1, 0.0f);
                    __nv_bfloat16 h0 = __float2bfloat16(v0);
                    __nv_bfloat16 h1 = __float2bfloat16(v1);
                    float l0 = v0 - __bfloat162float(h0);
                    float l1 = v1 - __bfloat162float(h1);
                    uint32_t hp = (uint32_t)*(unsigned short*)&h0 |
                                  ((uint32_t)*(unsigned short*)&h1 << 16);
                    ah[jj * 2 + pp] = hp;
                    al[jj * 2 + pp] = bfpack(l0, l1);
                }
            }
            // ---- layer2: accumulate D2 over this k-step (k = ch*128 + s*16) ----
#pragma unroll
            for (int j2 = 0; j2 < 16; j2++) {
                uint32_t b2h[2], b2l[2];
                const uint32_t b2base = j2 * 8 * SW2 * 2 + s * 32;
                ldsm_x2(b2h, uW2hi + b2base);
                ldsm_x2(b2l, uW2lo + b2base);
                mma_bf16(D2[j2], ah, b2h);
                mma_bf16(D2[j2], ah, b2l);
                mma_bf16(D2[j2], al, b2h);
            }
        }
    }

    // ---- layer3: out = relu(D2 + b2) . w3 + b3 ----
    float s0 = 0.0f, s1 = 0.0f;
#pragma unroll
    for (int j2 = 0; j2 < 16; j2++) {
        const int n2 = j2 * 8 + 2 * qp;
        const float w30 = w3s[n2], w31 = w3s[n2 + 1];
        const float bb0 = b2s[n2], bb1 = b2s[n2 + 1];
        s0 = fmaf(fmaxf(D2[j2][0] + bb0, 0.0f), w30, s0);
        s0 = fmaf(fmaxf(D2[j2][1] + bb1, 0.0f), w31, s0);
        s1 = fmaf(fmaxf(D2[j2][2] + bb0, 0.0f), w30, s1);
        s1 = fmaf(fmaxf(D2[j2][3] + bb1, 0.0f), w31, s1);
    }
    s0 += __shfl_xor_sync(0xffffffffu, s0, 1);
    s0 += __shfl_xor_sync(0xffffffffu, s0, 2);
    s1 += __shfl_xor_sync(0xffffffffu, s1, 1);
    s1 += __shfl_xor_sync(0xffffffffu, s1, 2);
    if (qp == 0) {
        const float bb = b3[0];
        const int m = w * 16 + qr;
        out[bid * 128 + m] = s0 + bb;
        out[bid * 128 + m + 8] = s1 + bb;
    }
}

// ---------------- launch ----------------
extern "C" void kernel_launch(void* const* d_in, const int* in_sizes, int n_in,
                              void* d_out, int out_size) {
    const float* x    = (const float*)d_in[0];
    const float* W_ih = (const float*)d_in[1];
    const float* W_hh = (const float*)d_in[2];
    const float* b_ih = (const float*)d_in[3];
    const float* b_hh = (const float*)d_in[4];
    const float* w1   = (const float*)d_in[5];
    const float* b1   = (const float*)d_in[6];
    const float* w2   = (const float*)d_in[7];
    const float* b2   = (const float*)d_in[8];
    const float* w3   = (const float*)d_in[9];
    const float* b3   = (const float*)d_in[10];
    float* out = (float*)d_out;

    prep_kernel<<<256, 256>>>(w1, w2);
    gru_kernel<<<ZB / NSEQ, 192>>>(x, W_ih, W_hh, b_ih, b_hh);

    static int attr_set = 0;
    if (!attr_set) {
        cudaFuncSetAttribute(mlp_kernel, cudaFuncAttributeMaxDynamicSharedMemorySize, SM_TOTAL);
        attr_set = 1;
    }
    mlp_kernel<<<ZB, 256, SM_TOTAL>>>(b1, b2, b3, w3, out);
}

// round 5
// speedup vs baseline: 3.2155x; 1.5583x over previous
#include <cuda_runtime.h>
#include <cuda_bf16.h>
#include <cuda_fp16.h>
#include <cstdint>

#define Bdim 32
#define Tdim 128
#define Zdim 100
#define Sdim 6
#define Hdim 64
#define F1 512
#define F2 128
#define ZB (Zdim * Bdim)          // 3200 sequences = 3200 MLP tiles of 128 rows
#define NROWS (ZB * Tdim)         // 409600

// ---------------- device scratch ----------------
// GRU outputs fp16, plain row-major A tiles: tile n rows t=0..127, cols k=0..63
__device__ __align__(16) __half g_a[NROWS * Hdim];
// w1 [512][64] fp16; w2 [128][512] fp16
__device__ __align__(16) __half g_w1h[F1 * Hdim];
__device__ __align__(16) __half g_w2h[F2 * F1];

// ---------------- packed fp32 helpers (GRU) ----------------
__device__ __forceinline__ void ffma2(unsigned long long &d, unsigned long long a, unsigned long long b) {
    asm("fma.rn.f32x2 %0, %1, %2, %0;" : "+l"(d) : "l"(a), "l"(b));
}
__device__ __forceinline__ unsigned long long pack2(float lo, float hi) {
    unsigned long long r; asm("mov.b64 %0, {%1, %2};" : "=l"(r) : "f"(lo), "f"(hi)); return r;
}
__device__ __forceinline__ float2 unpack2(unsigned long long v) {
    float2 r; asm("mov.b64 {%0, %1}, %2;" : "=f"(r.x), "=f"(r.y) : "l"(v)); return r;
}
__device__ __forceinline__ float sigmoidf_(float v) { return 1.0f / (1.0f + expf(-v)); }

// ---------------- mma / ldmatrix helpers ----------------
__device__ __forceinline__ uint32_t smem_u32(const void* p) {
    uint32_t a;
    asm("{ .reg .u64 t; cvta.to.shared.u64 t, %1; cvt.u32.u64 %0, t; }" : "=r"(a) : "l"(p));
    return a;
}
__device__ __forceinline__ void ldsm_x4(uint32_t* r, uint32_t addr) {
    asm volatile("ldmatrix.sync.aligned.m8n8.x4.shared.b16 {%0,%1,%2,%3}, [%4];"
                 : "=r"(r[0]), "=r"(r[1]), "=r"(r[2]), "=r"(r[3]) : "r"(addr));
}
__device__ __forceinline__ void ldsm_x2(uint32_t* r, uint32_t addr) {
    asm volatile("ldmatrix.sync.aligned.m8n8.x2.shared.b16 {%0,%1}, [%2];"
                 : "=r"(r[0]), "=r"(r[1]) : "r"(addr));
}
__device__ __forceinline__ void mma_fp16(float* d, const uint32_t* a, const uint32_t* b) {
    asm volatile("mma.sync.aligned.m16n8k16.row.col.f32.f16.f16.f32 "
                 "{%0,%1,%2,%3}, {%4,%5,%6,%7}, {%8,%9}, {%0,%1,%2,%3};"
                 : "+f"(d[0]), "+f"(d[1]), "+f"(d[2]), "+f"(d[3])
                 : "r"(a[0]), "r"(a[1]), "r"(a[2]), "r"(a[3]), "r"(b[0]), "r"(b[1]));
}
__device__ __forceinline__ uint32_t hpack(float x, float y) {
    __half2 t = __floats2half2_rn(x, y);
    return *(uint32_t*)&t;
}

// ---------------- weight prep: fp16 convert ----------------
__global__ void prep_kernel(const float* __restrict__ w1,
                            const float* __restrict__ w2) {
    int i = blockIdx.x * blockDim.x + threadIdx.x;
    if (i < F1 * Hdim) g_w1h[i] = __float2half(w1[i]);
    if (i < F2 * F1)   g_w2h[i] = __float2half(w2[i]);
}

// ---------------- GRU kernel ----------------
#define NSEQ 8
__global__ __launch_bounds__(192) void gru_kernel(
    const float* __restrict__ x,
    const float* __restrict__ Wih,
    const float* __restrict__ Whh,
    const float* __restrict__ bih,
    const float* __restrict__ bhh)
{
    __shared__ __align__(16) float h_sh[NSEQ][Hdim];
    __shared__ float r_sh[NSEQ][Hdim];
    __shared__ float z_sh[NSEQ][Hdim];
    __shared__ float xs[NSEQ][Sdim];

    const int g = threadIdx.x;
    const int n0 = blockIdx.x * NSEQ;
    const int zz = n0 >> 5;
    const int bb0 = n0 & 31;

    float wih[Sdim];
#pragma unroll
    for (int s = 0; s < Sdim; s++) wih[s] = Wih[g * Sdim + s];

    unsigned long long whh2[Hdim / 2];
    {
        const float2* wrow = (const float2*)(Whh + g * Hdim);
#pragma unroll
        for (int i = 0; i < Hdim / 2; i++) { float2 w = wrow[i]; whh2[i] = pack2(w.x, w.y); }
    }
    const float bi = bih[g];
    const float bh = bhh[g];

    for (int i = g; i < NSEQ * Hdim; i += 192) ((float*)h_sh)[i] = 0.0f;
    __syncthreads();

    const int j = g - 128;

    for (int t = 0; t < Tdim; t++) {
        if (g < NSEQ * Sdim) {
            int q = g / Sdim, s = g % Sdim;
            xs[q][s] = x[(((bb0 + q) * Tdim + t) * Zdim + zz) * Sdim + s];
        }
        __syncthreads();

        float gi[NSEQ], gh[NSEQ];
#pragma unroll
        for (int q = 0; q < NSEQ; q++) {
            float a = bi;
#pragma unroll
            for (int s = 0; s < Sdim; s++) a = fmaf(wih[s], xs[q][s], a);
            gi[q] = a;

            unsigned long long acc = 0ull;
            const ulonglong2* hp = (const ulonglong2*)h_sh[q];
#pragma unroll
            for (int i = 0; i < Hdim / 4; i++) {
                ulonglong2 hv = hp[i];
                ffma2(acc, whh2[2 * i], hv.x);
                ffma2(acc, whh2[2 * i + 1], hv.y);
            }
            float2 hv = unpack2(acc);
            gh[q] = bh + hv.x + hv.y;
        }

        if (g < 64) {
#pragma unroll
            for (int q = 0; q < NSEQ; q++) r_sh[q][g] = sigmoidf_(gi[q] + gh[q]);
        } else if (g < 128) {
#pragma unroll
            for (int q = 0; q < NSEQ; q++) z_sh[q][g - 64] = sigmoidf_(gi[q] + gh[q]);
        }
        __syncthreads();

        if (j >= 0) {
#pragma unroll
            for (int q = 0; q < NSEQ; q++) {
                float nn = tanhf(gi[q] + r_sh[q][j] * gh[q]);
                float zg = z_sh[q][j];
                float hn = nn + zg * (h_sh[q][j] - nn);
                h_sh[q][j] = hn;
                g_a[(n0 + q) * (Tdim * Hdim) + t * Hdim + j] = __float2half(hn);
            }
        }
        __syncthreads();
    }
}

// ---------------- tensor-core fused MLP (mma.sync fp16 single-pass) ----------------
// CTA = one sequence tile (M=128), 8 warps x 16 rows. Fused 64->512(relu)->128(relu)->1.
// Layer-1 D fragments feed layer-2 A fragments directly in registers.
#define SA1 72      // b16 stride of A1 smem rows (144B: conflict-free ldmatrix)
#define SW1 72
#define SW2 136     // 272B
#define OFF_A1 0
#define OFF_W1 18432
#define OFF_W2 36864
#define OFF_B1 71680
#define OFF_B2 73728
#define OFF_W3 74240
#define SM_TOTAL 74752

__global__ __launch_bounds__(256, 2) void mlp_kernel(
    const float* __restrict__ b1,
    const float* __restrict__ b2,
    const float* __restrict__ b3,
    const float* __restrict__ w3,
    float* __restrict__ out)
{
    extern __shared__ char sm[];
    const int tid = threadIdx.x;
    const int w = tid >> 5;
    const int lane = tid & 31;
    const int qp = lane & 3;        // quad position (n/k pair index)
    const int qr = lane >> 2;       // quad row (m within 8)
    const int bid = blockIdx.x;

    float* b1s = (float*)(sm + OFF_B1);
    float* b2s = (float*)(sm + OFF_B2);
    float* w3s = (float*)(sm + OFF_W3);
    for (int i = tid; i < F1; i += 256) b1s[i] = b1[i];
    if (tid < F2) { b2s[tid] = b2[tid]; w3s[tid] = w3[tid]; }

    // ---- stage A1 tile, rows stride SA1 ----
    {
        const uint4* sp = (const uint4*)(g_a + (size_t)bid * (Tdim * Hdim));
        for (int i = tid; i < 1024; i += 256) {
            int r = i >> 3, c = i & 7;
            *(uint4*)(sm + OFF_A1 + r * (SA1 * 2) + c * 16) = sp[i];
        }
    }
    __syncthreads();

    // ---- per-lane ldmatrix addresses ----
    const int arow = w * 16 + ((lane >> 3) & 1) * 8 + (lane & 7);
    const int acol = ((lane >> 4) & 1) * 8;
    const uint32_t uA1 = smem_u32(sm + OFF_A1) + (arow * SA1 + acol) * 2;
    const int Lb = lane & 15;
    const int brow = Lb & 7;
    const int bkof = (Lb >> 3) * 8;
    const uint32_t uW1 = smem_u32(sm + OFF_W1) + (brow * SW1 + bkof) * 2;
    const uint32_t uW2 = smem_u32(sm + OFF_W2) + (brow * SW2 + bkof) * 2;

    // ---- load A1 fragments once (4 k-steps) ----
    uint32_t Ah[4][4];
#pragma unroll
    for (int kk = 0; kk < 4; kk++) ldsm_x4(Ah[kk], uA1 + kk * 32);

    float D2[16][4];
#pragma unroll
    for (int j = 0; j < 16; j++)
#pragma unroll
        for (int p = 0; p < 4; p++) D2[j][p] = 0.0f;

    for (int ch = 0; ch < 4; ch++) {
        __syncthreads();   // protect W buffers from previous iteration's readers
        // stage W1 chunk [128][64]
        {
            const uint4* s0 = (const uint4*)(g_w1h + ch * 128 * Hdim);
            for (int i = tid; i < 1024; i += 256) {
                int r = i >> 3, c = i & 7;
                *(uint4*)(sm + OFF_W1 + r * (SW1 * 2) + c * 16) = s0[i];
            }
        }
        // stage W2 chunk [128][128] (k-slice ch*128)
        {
            for (int i = tid; i < 2048; i += 256) {
                int r = i >> 4, c = i & 15;
                *(uint4*)(sm + OFF_W2 + r * (SW2 * 2) + c * 16) =
                    *(const uint4*)(g_w2h + r * F1 + ch * 128 + c * 8);
            }
        }
        __syncthreads();

#pragma unroll 1
        for (int s = 0; s < 8; s++) {
            // ---- layer1: two n-tiles (n = ch*128 + (2s+jj)*8 ...) ----
            float D1[2][4];
#pragma unroll
            for (int jj = 0; jj < 2; jj++) {
#pragma unroll
                for (int p = 0; p < 4; p++) D1[jj][p] = 0.0f;
                const int j = 2 * s + jj;
                const uint32_t b_base = uW1 + j * 8 * SW1 * 2;
#pragma unroll
                for (int kk = 0; kk < 4; kk++) {
                    uint32_t bh[2];
                    ldsm_x2(bh, b_base + kk * 32);
                    mma_fp16(D1[jj], Ah[kk], bh);
                }
            }
            // ---- epilogue: relu(D1+b1) -> fp16 -> layer2 A fragments ----
            uint32_t ah[4];
#pragma unroll
            for (int jj = 0; jj < 2; jj++) {
                const int nb = ch * 128 + (2 * s + jj) * 8 + 2 * qp;
                const float bb0 = b1s[nb], bb1 = b1s[nb + 1];
#pragma unroll
                for (int pp = 0; pp < 2; pp++) {
                    float v0 = fmaxf(D1[jj][2 * pp] + bb0, 0.0f);
                    float v1 = fmaxf(D1[jj][2 * pp + 1] + bb1, 0.0f);
                    ah[jj * 2 + pp] = hpack(v0, v1);
                }
            }
            // ---- layer2: accumulate D2 over this k-step (k = ch*128 + s*16) ----
#pragma unroll
            for (int j2 = 0; j2 < 16; j2++) {
                uint32_t b2f[2];
                ldsm_x2(b2f, uW2 + j2 * 8 * SW2 * 2 + s * 32);
                mma_fp16(D2[j2], ah, b2f);
            }
        }
    }

    // ---- layer3: out = relu(D2 + b2) . w3 + b3 ----
    float s0 = 0.0f, s1 = 0.0f;
#pragma unroll
    for (int j2 = 0; j2 < 16; j2++) {
        const int n2 = j2 * 8 + 2 * qp;
        const float w30 = w3s[n2], w31 = w3s[n2 + 1];
        const float bb0 = b2s[n2], bb1 = b2s[n2 + 1];
        s0 = fmaf(fmaxf(D2[j2][0] + bb0, 0.0f), w30, s0);
        s0 = fmaf(fmaxf(D2[j2][1] + bb1, 0.0f), w31, s0);
        s1 = fmaf(fmaxf(D2[j2][2] + bb0, 0.0f), w30, s1);
        s1 = fmaf(fmaxf(D2[j2][3] + bb1, 0.0f), w31, s1);
    }
    s0 += __shfl_xor_sync(0xffffffffu, s0, 1);
    s0 += __shfl_xor_sync(0xffffffffu, s0, 2);
    s1 += __shfl_xor_sync(0xffffffffu, s1, 1);
    s1 += __shfl_xor_sync(0xffffffffu, s1, 2);
    if (qp == 0) {
        const float bb = b3[0];
        const int m = w * 16 + qr;
        out[bid * 128 + m] = s0 + bb;
        out[bid * 128 + m + 8] = s1 + bb;
    }
}

// ---------------- launch ----------------
extern "C" void kernel_launch(void* const* d_in, const int* in_sizes, int n_in,
                              void* d_out, int out_size) {
    const float* x    = (const float*)d_in[0];
    const float* W_ih = (const float*)d_in[1];
    const float* W_hh = (const float*)d_in[2];
    const float* b_ih = (const float*)d_in[3];
    const float* b_hh = (const float*)d_in[4];
    const float* w1   = (const float*)d_in[5];
    const float* b1   = (const float*)d_in[6];
    const float* w2   = (const float*)d_in[7];
    const float* b2   = (const float*)d_in[8];
    const float* w3   = (const float*)d_in[9];
    const float* b3   = (const float*)d_in[10];
    float* out = (float*)d_out;

    prep_kernel<<<256, 256>>>(w1, w2);
    gru_kernel<<<ZB / NSEQ, 192>>>(x, W_ih, W_hh, b_ih, b_hh);

    static int attr_set = 0;
    if (!attr_set) {
        cudaFuncSetAttribute(mlp_kernel, cudaFuncAttributeMaxDynamicSharedMemorySize, SM_TOTAL);
        attr_set = 1;
    }
    mlp_kernel<<<ZB, 256, SM_TOTAL>>>(b1, b2, b3, w3, out);
}

// round 6
// speedup vs baseline: 3.8830x; 1.2076x over previous
#include <cuda_runtime.h>
#include <cuda_fp16.h>
#include <cstdint>

#define Bdim 32
#define Tdim 128
#define Zdim 100
#define Sdim 6
#define Hdim 64
#define F1 512
#define F2 128
#define ZB (Zdim * Bdim)          // 3200 sequences = 3200 MLP tiles of 128 rows
#define NROWS (ZB * Tdim)         // 409600

// ---------------- device scratch ----------------
__device__ __align__(16) __half g_a[NROWS * Hdim];   // GRU outputs fp16, row-major tiles
__device__ __align__(16) __half g_w1h[F1 * Hdim];    // w1 [512][64] fp16
__device__ __align__(16) __half g_w2h[F2 * F1];      // w2 [128][512] fp16

// ---------------- packed fp32 helpers (GRU) ----------------
__device__ __forceinline__ void ffma2(unsigned long long &d, unsigned long long a, unsigned long long b) {
    asm("fma.rn.f32x2 %0, %1, %2, %0;" : "+l"(d) : "l"(a), "l"(b));
}
__device__ __forceinline__ unsigned long long pack2(float lo, float hi) {
    unsigned long long r; asm("mov.b64 %0, {%1, %2};" : "=l"(r) : "f"(lo), "f"(hi)); return r;
}
__device__ __forceinline__ float2 unpack2(unsigned long long v) {
    float2 r; asm("mov.b64 {%0, %1}, %2;" : "=f"(r.x), "=f"(r.y) : "l"(v)); return r;
}
// fast activations: ex2/rcp approx paths, added error ~1e-6 (safe for recurrence)
__device__ __forceinline__ float sigmoid_fast(float v) {
    return __fdividef(1.0f, 1.0f + __expf(-v));
}
__device__ __forceinline__ float tanh_fast(float v) {
    float e = __expf(2.0f * v);
    return 1.0f - __fdividef(2.0f, e + 1.0f);
}

// ---------------- mma / ldmatrix helpers ----------------
__device__ __forceinline__ uint32_t smem_u32(const void* p) {
    uint32_t a;
    asm("{ .reg .u64 t; cvta.to.shared.u64 t, %1; cvt.u32.u64 %0, t; }" : "=r"(a) : "l"(p));
    return a;
}
__device__ __forceinline__ void ldsm_x4(uint32_t* r, uint32_t addr) {
    asm volatile("ldmatrix.sync.aligned.m8n8.x4.shared.b16 {%0,%1,%2,%3}, [%4];"
                 : "=r"(r[0]), "=r"(r[1]), "=r"(r[2]), "=r"(r[3]) : "r"(addr));
}
__device__ __forceinline__ void mma_fp16(float* d, const uint32_t* a, const uint32_t* b) {
    asm volatile("mma.sync.aligned.m16n8k16.row.col.f32.f16.f16.f32 "
                 "{%0,%1,%2,%3}, {%4,%5,%6,%7}, {%8,%9}, {%0,%1,%2,%3};"
                 : "+f"(d[0]), "+f"(d[1]), "+f"(d[2]), "+f"(d[3])
                 : "r"(a[0]), "r"(a[1]), "r"(a[2]), "r"(a[3]), "r"(b[0]), "r"(b[1]));
}
__device__ __forceinline__ uint32_t hpack(float x, float y) {
    __half2 t = __floats2half2_rn(x, y);
    return *(uint32_t*)&t;
}

// ---------------- weight prep: fp16 convert ----------------
__global__ void prep_kernel(const float* __restrict__ w1,
                            const float* __restrict__ w2) {
    int i = blockIdx.x * blockDim.x + threadIdx.x;
    if (i < F1 * Hdim) g_w1h[i] = __float2half(w1[i]);
    if (i < F2 * F1)   g_w2h[i] = __float2half(w2[i]);
}

// ---------------- GRU kernel ----------------
#define NSEQ 8
__global__ __launch_bounds__(192) void gru_kernel(
    const float* __restrict__ x,
    const float* __restrict__ Wih,
    const float* __restrict__ Whh,
    const float* __restrict__ bih,
    const float* __restrict__ bhh)
{
    __shared__ __align__(16) float h_sh[NSEQ][Hdim];
    __shared__ float r_sh[NSEQ][Hdim];
    __shared__ float z_sh[NSEQ][Hdim];
    __shared__ float xs[2][NSEQ][Sdim];

    const int g = threadIdx.x;
    const int n0 = blockIdx.x * NSEQ;
    const int zz = n0 >> 5;
    const int bb0 = n0 & 31;

    float wih[Sdim];
#pragma unroll
    for (int s = 0; s < Sdim; s++) wih[s] = Wih[g * Sdim + s];

    unsigned long long whh2[Hdim / 2];
    {
        const float2* wrow = (const float2*)(Whh + g * Hdim);
#pragma unroll
        for (int i = 0; i < Hdim / 2; i++) { float2 w = wrow[i]; whh2[i] = pack2(w.x, w.y); }
    }
    const float bi = bih[g];
    const float bh = bhh[g];

    for (int i = g; i < NSEQ * Hdim; i += 192) ((float*)h_sh)[i] = 0.0f;

    const int lq = g / Sdim, ls = g % Sdim;     // loader mapping (g < 48)
    if (g < NSEQ * Sdim)
        xs[0][lq][ls] = x[(((bb0 + lq) * Tdim + 0) * Zdim + zz) * Sdim + ls];
    __syncthreads();

    const int j = g - 128;   // n-gate threads also do the h update

    for (int t = 0; t < Tdim; t++) {
        const int cur = t & 1;

        // ---- phase 1: dots (i-outer, 8 independent acc chains) ----
        float gi[NSEQ];
#pragma unroll
        for (int q = 0; q < NSEQ; q++) {
            float a = bi;
#pragma unroll
            for (int s = 0; s < Sdim; s++) a = fmaf(wih[s], xs[cur][q][s], a);
            gi[q] = a;
        }
        unsigned long long acc[NSEQ];
#pragma unroll
        for (int q = 0; q < NSEQ; q++) acc[q] = 0ull;
#pragma unroll
        for (int i = 0; i < Hdim / 4; i++) {
#pragma unroll
            for (int q = 0; q < NSEQ; q++) {
                ulonglong2 hv = ((const ulonglong2*)h_sh[q])[i];
                ffma2(acc[q], whh2[2 * i], hv.x);
                ffma2(acc[q], whh2[2 * i + 1], hv.y);
            }
        }
        float gh[NSEQ];
#pragma unroll
        for (int q = 0; q < NSEQ; q++) {
            float2 hv = unpack2(acc[q]);
            gh[q] = bh + hv.x + hv.y;
        }

        // prefetch x[t+1] (loader threads)
        if (g < NSEQ * Sdim && t + 1 < Tdim)
            xs[cur ^ 1][lq][ls] = x[(((bb0 + lq) * Tdim + (t + 1)) * Zdim + zz) * Sdim + ls];

        if (g < 64) {
#pragma unroll
            for (int q = 0; q < NSEQ; q++) r_sh[q][g] = sigmoid_fast(gi[q] + gh[q]);
        } else if (g < 128) {
#pragma unroll
            for (int q = 0; q < NSEQ; q++) z_sh[q][g - 64] = sigmoid_fast(gi[q] + gh[q]);
        }
        __syncthreads();

        // ---- phase 2: n gate + h update (threads 128..191) ----
        if (j >= 0) {
#pragma unroll
            for (int q = 0; q < NSEQ; q++) {
                float nn = tanh_fast(gi[q] + r_sh[q][j] * gh[q]);
                float zg = z_sh[q][j];
                float hn = nn + zg * (h_sh[q][j] - nn);
                h_sh[q][j] = hn;
                g_a[(n0 + q) * (Tdim * Hdim) + t * Hdim + j] = __float2half(hn);
            }
        }
        __syncthreads();
    }
}

// ---------------- tensor-core fused MLP (mma.sync fp16) ----------------
// CTA = one sequence tile (M=128), 8 warps x 16 rows. Fused 64->512(relu)->128(relu)->1.
#define SA1 72      // b16 stride (144B: conflict-free ldmatrix)
#define SW1 72
#define SW2 136     // 272B
#define OFF_A1 0
#define OFF_W1 18432
#define OFF_W2 36864
#define OFF_B1 71680
#define OFF_B2 73728
#define OFF_W3 74240
#define SM_TOTAL 74752

__global__ __launch_bounds__(256, 2) void mlp_kernel(
    const float* __restrict__ b1,
    const float* __restrict__ b2,
    const float* __restrict__ b3,
    const float* __restrict__ w3,
    float* __restrict__ out)
{
    extern __shared__ char sm[];
    const int tid = threadIdx.x;
    const int w = tid >> 5;
    const int lane = tid & 31;
    const int qp = lane & 3;
    const int qr = lane >> 2;
    const int bid = blockIdx.x;

    float* b1s = (float*)(sm + OFF_B1);
    float* b2s = (float*)(sm + OFF_B2);
    float* w3s = (float*)(sm + OFF_W3);
    for (int i = tid; i < F1; i += 256) b1s[i] = b1[i];
    if (tid < F2) { b2s[tid] = b2[tid]; w3s[tid] = w3[tid]; }

    // ---- stage A1 tile ----
    {
        const uint4* sp = (const uint4*)(g_a + (size_t)bid * (Tdim * Hdim));
        for (int i = tid; i < 1024; i += 256) {
            int r = i >> 3, c = i & 7;
            *(uint4*)(sm + OFF_A1 + r * (SA1 * 2) + c * 16) = sp[i];
        }
    }
    __syncthreads();

    // ---- per-lane ldmatrix addresses ----
    const int arow = w * 16 + ((lane >> 3) & 1) * 8 + (lane & 7);
    const int acol = ((lane >> 4) & 1) * 8;
    const uint32_t uA1 = smem_u32(sm + OFF_A1) + (arow * SA1 + acol) * 2;
    // W1 x4: 4 mats = k-quarters 0..3, rows n = j*8 + (lane&7)
    const uint32_t uW1x4 = smem_u32(sm + OFF_W1) + ((lane & 7) * SW1 + (lane >> 3) * 8) * 2;
    // W2 x4: mats = {j2 k0-7, j2 k8-15, j2+1 k0-7, j2+1 k8-15}
    const uint32_t uW2x4 = smem_u32(sm + OFF_W2) +
        ((((lane >> 4) * 8 + (lane & 7)) * SW2) + ((lane >> 3) & 1) * 8) * 2;

    // ---- load A1 fragments once (4 k-steps) ----
    uint32_t Ah[4][4];
#pragma unroll
    for (int kk = 0; kk < 4; kk++) ldsm_x4(Ah[kk], uA1 + kk * 32);

    float D2[16][4];
#pragma unroll
    for (int jj = 0; jj < 16; jj++)
#pragma unroll
        for (int p = 0; p < 4; p++) D2[jj][p] = 0.0f;

    for (int ch = 0; ch < 4; ch++) {
        __syncthreads();   // protect W buffers from previous iteration's readers
        {
            const uint4* s0 = (const uint4*)(g_w1h + ch * 128 * Hdim);
            for (int i = tid; i < 1024; i += 256) {
                int r = i >> 3, c = i & 7;
                *(uint4*)(sm + OFF_W1 + r * (SW1 * 2) + c * 16) = s0[i];
            }
        }
        {
            for (int i = tid; i < 2048; i += 256) {
                int r = i >> 4, c = i & 15;
                *(uint4*)(sm + OFF_W2 + r * (SW2 * 2) + c * 16) =
                    *(const uint4*)(g_w2h + r * F1 + ch * 128 + c * 8);
            }
        }
        __syncthreads();

#pragma unroll 1
        for (int s = 0; s < 8; s++) {
            // ---- layer1: two n-tiles ----
            float D1[2][4];
#pragma unroll
            for (int jj = 0; jj < 2; jj++) {
#pragma unroll
                for (int p = 0; p < 4; p++) D1[jj][p] = 0.0f;
                const int jn = 2 * s + jj;
                const uint32_t bb = uW1x4 + jn * 8 * SW1 * 2;
                uint32_t bf[8];                // k-quarters 0-3 -> 4 k16-steps
                ldsm_x4(bf, bb);               // k 0..31
                ldsm_x4(bf + 4, bb + 64);      // k 32..63
#pragma unroll
                for (int kk = 0; kk < 4; kk++) mma_fp16(D1[jj], Ah[kk], bf + 2 * kk);
            }
            // ---- epilogue: relu(D1+b1) -> fp16 A2 fragments ----
            uint32_t ah[4];
#pragma unroll
            for (int jj = 0; jj < 2; jj++) {
                const int nb = ch * 128 + (2 * s + jj) * 8 + 2 * qp;
                const float bb0 = b1s[nb], bb1 = b1s[nb + 1];
#pragma unroll
                for (int pp = 0; pp < 2; pp++) {
                    float v0 = fmaxf(D1[jj][2 * pp] + bb0, 0.0f);
                    float v1 = fmaxf(D1[jj][2 * pp + 1] + bb1, 0.0f);
                    ah[jj * 2 + pp] = hpack(v0, v1);
                }
            }
            // ---- layer2: accumulate (k = ch*128 + s*16), j2 pairs via x4 ----
#pragma unroll
            for (int j2 = 0; j2 < 16; j2 += 2) {
                uint32_t bf[4];
                ldsm_x4(bf, uW2x4 + j2 * 8 * SW2 * 2 + s * 32);
                mma_fp16(D2[j2], ah, bf);
                mma_fp16(D2[j2 + 1], ah, bf + 2);
            }
        }
    }

    // ---- layer3: out = relu(D2 + b2) . w3 + b3 ----
    float s0 = 0.0f, s1 = 0.0f;
#pragma unroll
    for (int j2 = 0; j2 < 16; j2++) {
        const int n2 = j2 * 8 + 2 * qp;
        const float w30 = w3s[n2], w31 = w3s[n2 + 1];
        const float bb0 = b2s[n2], bb1 = b2s[n2 + 1];
        s0 = fmaf(fmaxf(D2[j2][0] + bb0, 0.0f), w30, s0);
        s0 = fmaf(fmaxf(D2[j2][1] + bb1, 0.0f), w31, s0);
        s1 = fmaf(fmaxf(D2[j2][2] + bb0, 0.0f), w30, s1);
        s1 = fmaf(fmaxf(D2[j2][3] + bb1, 0.0f), w31, s1);
    }
    s0 += __shfl_xor_sync(0xffffffffu, s0, 1);
    s0 += __shfl_xor_sync(0xffffffffu, s0, 2);
    s1 += __shfl_xor_sync(0xffffffffu, s1, 1);
    s1 += __shfl_xor_sync(0xffffffffu, s1, 2);
    if (qp == 0) {
        const float bb = b3[0];
        const int m = w * 16 + qr;
        out[bid * 128 + m] = s0 + bb;
        out[bid * 128 + m + 8] = s1 + bb;
    }
}

// ---------------- launch ----------------
extern "C" void kernel_launch(void* const* d_in, const int* in_sizes, int n_in,
                              void* d_out, int out_size) {
    const float* x    = (const float*)d_in[0];
    const float* W_ih = (const float*)d_in[1];
    const float* W_hh = (const float*)d_in[2];
    const float* b_ih = (const float*)d_in[3];
    const float* b_hh = (const float*)d_in[4];
    const float* w1   = (const float*)d_in[5];
    const float* b1   = (const float*)d_in[6];
    const float* w2   = (const float*)d_in[7];
    const float* b2   = (const float*)d_in[8];
    const float* w3   = (const float*)d_in[9];
    const float* b3   = (const float*)d_in[10];
    float* out = (float*)d_out;

    prep_kernel<<<256, 256>>>(w1, w2);
    gru_kernel<<<ZB / NSEQ, 192>>>(x, W_ih, W_hh, b_ih, b_hh);

    static int attr_set = 0;
    if (!attr_set) {
        cudaFuncSetAttribute(mlp_kernel, cudaFuncAttributeMaxDynamicSharedMemorySize, SM_TOTAL);
        attr_set = 1;
    }
    mlp_kernel<<<ZB, 256, SM_TOTAL>>>(b1, b2, b3, w3, out);
}

// round 7
// speedup vs baseline: 8.0738x; 2.0792x over previous
#include <cuda_runtime.h>
#include <cuda_fp16.h>
#include <cstdint>

#define Bdim 32
#define Tdim 128
#define Zdim 100
#define Sdim 6
#define Hdim 64
#define F1 512
#define F2 128
#define ZB (Zdim * Bdim)          // 3200 sequences
#define NROWS (ZB * Tdim)         // 409600

// ---------------- device scratch ----------------
__device__ __align__(16) __half g_a[NROWS * Hdim];   // GRU outputs fp16, row-major tiles
__device__ __align__(16) __half g_w1h[F1 * Hdim];    // w1 [512][64] fp16
__device__ __align__(16) __half g_w2h[F2 * F1];      // w2 [128][512] fp16

// ---------------- helpers ----------------
__device__ __forceinline__ float sigmoid_fast(float v) {
    return __fdividef(1.0f, 1.0f + __expf(-v));
}
__device__ __forceinline__ float tanh_fast(float v) {
    float e = __expf(2.0f * v);
    return 1.0f - __fdividef(2.0f, e + 1.0f);
}
__device__ __forceinline__ uint32_t smem_u32(const void* p) {
    uint32_t a;
    asm("{ .reg .u64 t; cvta.to.shared.u64 t, %1; cvt.u32.u64 %0, t; }" : "=r"(a) : "l"(p));
    return a;
}
__device__ __forceinline__ void ldsm_x4(uint32_t* r, uint32_t addr) {
    asm volatile("ldmatrix.sync.aligned.m8n8.x4.shared.b16 {%0,%1,%2,%3}, [%4];"
                 : "=r"(r[0]), "=r"(r[1]), "=r"(r[2]), "=r"(r[3]) : "r"(addr));
}
__device__ __forceinline__ void ldsm_x2(uint32_t* r, uint32_t addr) {
    asm volatile("ldmatrix.sync.aligned.m8n8.x2.shared.b16 {%0,%1}, [%2];"
                 : "=r"(r[0]), "=r"(r[1]) : "r"(addr));
}
__device__ __forceinline__ void mma_fp16(float* d, const uint32_t* a, const uint32_t* b) {
    asm volatile("mma.sync.aligned.m16n8k16.row.col.f32.f16.f16.f32 "
                 "{%0,%1,%2,%3}, {%4,%5,%6,%7}, {%8,%9}, {%0,%1,%2,%3};"
                 : "+f"(d[0]), "+f"(d[1]), "+f"(d[2]), "+f"(d[3])
                 : "r"(a[0]), "r"(a[1]), "r"(a[2]), "r"(a[3]), "r"(b[0]), "r"(b[1]));
}
__device__ __forceinline__ uint32_t hpack(float x, float y) {
    __half2 t = __floats2half2_rn(x, y);
    return *(uint32_t*)&t;
}
__device__ __forceinline__ uint32_t hpackh(__half x, __half y) {
    return (uint32_t)*(unsigned short*)&x | ((uint32_t)*(unsigned short*)&y << 16);
}

// ---------------- weight prep: fp16 convert ----------------
__global__ void prep_kernel(const float* __restrict__ w1,
                            const float* __restrict__ w2) {
    int i = blockIdx.x * blockDim.x + threadIdx.x;
    if (i < F1 * Hdim) g_w1h[i] = __float2half(w1[i]);
    if (i < F2 * F1)   g_w2h[i] = __float2half(w2[i]);
}

// ---------------- tensor-core GRU ----------------
// CTA = one zone = 32 sequences. h in smem fp32; A = h hi/lo fp16;
// W_hh/W_ih B-frags register-resident. Warp w owns n-tiles {w, 8+w, 16+w}
// = gates r,z,n for h-cols [8w, 8w+8) -> lane-local gate combine.
#define GOFF_H    0                      // float h[32][66]           8448 B
#define GOFF_WHH  8448                   // half  whh[192][72]       27648 B
#define GOFF_WIH  36096                  // half  wih[192][24]        9216 B
#define GOFF_AH   45312                  // half  ah[32][72]          4608 B
#define GOFF_AL   49920                  // half  al[32][72]          4608 B
#define GOFF_XA   54528                  // half  xa[2][32][24]       3072 B
#define GSM_TOTAL 57600

__global__ __launch_bounds__(256, 1) void gru_kernel(
    const float* __restrict__ x,
    const float* __restrict__ Wih,
    const float* __restrict__ Whh,
    const float* __restrict__ bihp,
    const float* __restrict__ bhhp)
{
    extern __shared__ char gsm[];
    float* h_sh  = (float*)(gsm + GOFF_H);
    __half* whh_s = (__half*)(gsm + GOFF_WHH);
    __half* wih_s = (__half*)(gsm + GOFF_WIH);
    __half* ah_s  = (__half*)(gsm + GOFF_AH);
    __half* al_s  = (__half*)(gsm + GOFF_AL);
    __half* xa_s  = (__half*)(gsm + GOFF_XA);

    const int tid = threadIdx.x;
    const int w = tid >> 5;
    const int lane = tid & 31;
    const int qp = lane & 3;
    const int qr = lane >> 2;
    const int zz = blockIdx.x;           // zone
    const int nseq0 = zz * 32;

    // ---- zero h, wih pad, ah/al/xa ----
    for (int i = tid; i < 2112; i += 256) ((float*)(gsm + GOFF_H))[i] = 0.0f;
    for (int i = tid; i < 2304; i += 256) ((uint32_t*)(gsm + GOFF_WIH))[i] = 0u;
    for (int i = tid; i < 3072; i += 256) ((uint32_t*)(gsm + GOFF_AH))[i] = 0u;

    // ---- stage W_hh [192][64] -> fp16 stride 72 ----
    for (int i = tid; i < 192 * 64; i += 256)
        whh_s[(i >> 6) * 72 + (i & 63)] = __float2half(Whh[i]);
    __syncthreads();   // wih zero before writing data cols
    // ---- stage W_ih [192][6] -> fp16 stride 24 (cols 6..23 zero) ----
    for (int i = tid; i < 192 * 6; i += 256)
        wih_s[(i / 6) * 24 + (i % 6)] = __float2half(Wih[i]);
    // ---- stage x(t=0) into xa[0] ----
    const int q = tid / 6, s = tid - (tid / 6) * 6;   // valid for tid<192
    if (tid < 192)
        xa_s[q * 24 + s] = __float2half(x[((q * Tdim + 0) * Zdim + zz) * Sdim + s]);
    __syncthreads();

    // ---- register-resident B fragments ----
    const uint32_t uWhh = smem_u32(whh_s);
    const uint32_t uWih = smem_u32(wih_s);
    const int Lb = lane & 15;
    uint32_t Bhh[3][4][2], Bih[3][2];
#pragma unroll
    for (int g = 0; g < 3; g++) {
        const int ng = g * 64 + w * 8;
        uint32_t r4[4];
        ldsm_x4(r4, uWhh + (uint32_t)(ng + (lane & 7)) * 144 + (uint32_t)(lane >> 3) * 16);
        Bhh[g][0][0] = r4[0]; Bhh[g][0][1] = r4[1];
        Bhh[g][1][0] = r4[2]; Bhh[g][1][1] = r4[3];
        ldsm_x4(r4, uWhh + (uint32_t)(ng + (lane & 7)) * 144 + (uint32_t)(lane >> 3) * 16 + 64);
        Bhh[g][2][0] = r4[0]; Bhh[g][2][1] = r4[1];
        Bhh[g][3][0] = r4[2]; Bhh[g][3][1] = r4[3];
        ldsm_x2(Bih[g], uWih + (uint32_t)(ng + (Lb & 7)) * 48 + (uint32_t)(Lb >> 3) * 16);
    }

    // ---- per-lane biases ----
    const int cb = w * 8 + 2 * qp;       // h-col base for this lane
    const float brz0 = bihp[cb]       + bhhp[cb];
    const float brz1 = bihp[cb + 1]   + bhhp[cb + 1];
    const float bz0  = bihp[64 + cb]  + bhhp[64 + cb];
    const float bz1  = bihp[64 + cb + 1] + bhhp[64 + cb + 1];
    const float bin0 = bihp[128 + cb],     bin1 = bihp[128 + cb + 1];
    const float bhn0 = bhhp[128 + cb],     bhn1 = bhhp[128 + cb + 1];

    // ---- per-lane ldmatrix A addressing ----
    const int arow_lo = ((lane >> 3) & 1) * 8 + (lane & 7);
    const uint32_t acolb = (uint32_t)((lane >> 4) & 1) * 16;
    const uint32_t uAH = smem_u32(ah_s);
    const uint32_t uAL = smem_u32(al_s);
    const uint32_t uXA = smem_u32(xa_s);

    for (int t = 0; t < Tdim; t++) {
        const int cur = t & 1;

        // ---- ldsm A fragments (h hi/lo, x) ----
        uint32_t Ahi[2][4][4], Alo[2][4][4], Ax[2][4];
#pragma unroll
        for (int mt = 0; mt < 2; mt++) {
            const uint32_t rb = (uint32_t)(mt * 16 + arow_lo);
#pragma unroll
            for (int kk = 0; kk < 4; kk++) {
                ldsm_x4(Ahi[mt][kk], uAH + rb * 144 + acolb + kk * 32);
                ldsm_x4(Alo[mt][kk], uAL + rb * 144 + acolb + kk * 32);
            }
            ldsm_x4(Ax[mt], uXA + (uint32_t)cur * 1536 + rb * 48 + acolb);
        }
        // prefetch x(t+1)
        float xvn = 0.0f;
        if (tid < 192 && t + 1 < Tdim)
            xvn = x[((q * Tdim + (t + 1)) * Zdim + zz) * Sdim + s];
        __syncthreads();   // all ldsm reads done before epilogue writes

#pragma unroll
        for (int mt = 0; mt < 2; mt++) {
            float Dh[3][4], Dg[3][4];
#pragma unroll
            for (int g = 0; g < 3; g++) {
#pragma unroll
                for (int p = 0; p < 4; p++) { Dh[g][p] = 0.0f; Dg[g][p] = 0.0f; }
#pragma unroll
                for (int kk = 0; kk < 4; kk++) mma_fp16(Dh[g], Ahi[mt][kk], Bhh[g][kk]);
#pragma unroll
                for (int kk = 0; kk < 4; kk++) mma_fp16(Dh[g], Alo[mt][kk], Bhh[g][kk]);
                mma_fp16(Dg[g], Ax[mt], Bih[g]);
            }
            // ---- epilogue: gates + h update ----
#pragma unroll
            for (int rr = 0; rr < 2; rr++) {
                const int seqr = mt * 16 + rr * 8 + qr;
                const int i0 = rr * 2, i1 = rr * 2 + 1;
                float r0 = sigmoid_fast(Dg[0][i0] + Dh[0][i0] + brz0);
                float r1 = sigmoid_fast(Dg[0][i1] + Dh[0][i1] + brz1);
                float z0 = sigmoid_fast(Dg[1][i0] + Dh[1][i0] + bz0);
                float z1 = sigmoid_fast(Dg[1][i1] + Dh[1][i1] + bz1);
                float nn0 = tanh_fast(Dg[2][i0] + bin0 + r0 * (Dh[2][i0] + bhn0));
                float nn1 = tanh_fast(Dg[2][i1] + bin1 + r1 * (Dh[2][i1] + bhn1));
                float h0 = h_sh[seqr * 66 + cb];
                float h1 = h_sh[seqr * 66 + cb + 1];
                float hn0 = nn0 + z0 * (h0 - nn0);
                float hn1 = nn1 + z1 * (h1 - nn1);
                h_sh[seqr * 66 + cb]     = hn0;
                h_sh[seqr * 66 + cb + 1] = hn1;
                __half hi0 = __float2half(hn0), hi1 = __float2half(hn1);
                __half lo0 = __float2half(hn0 - __half2float(hi0));
                __half lo1 = __float2half(hn1 - __half2float(hi1));
                *(uint32_t*)&ah_s[seqr * 72 + cb] = hpackh(hi0, hi1);
                *(uint32_t*)&al_s[seqr * 72 + cb] = hpackh(lo0, lo1);
                *(uint32_t*)&g_a[(size_t)(nseq0 + seqr) * (Tdim * Hdim) + t * Hdim + cb]
                    = hpackh(hi0, hi1);
            }
        }
        // store x(t+1) into alternate buffer
        if (tid < 192 && t + 1 < Tdim)
            xa_s[(cur ^ 1) * 768 + q * 24 + s] = __float2half(xvn);
        __syncthreads();
    }
}

// ---------------- tensor-core fused MLP (unchanged from R6) ----------------
#define SA1 72
#define SW1 72
#define SW2 136
#define OFF_A1 0
#define OFF_W1 18432
#define OFF_W2 36864
#define OFF_B1 71680
#define OFF_B2 73728
#define OFF_W3 74240
#define SM_TOTAL 74752

__global__ __launch_bounds__(256, 2) void mlp_kernel(
    const float* __restrict__ b1,
    const float* __restrict__ b2,
    const float* __restrict__ b3,
    const float* __restrict__ w3,
    float* __restrict__ out)
{
    extern __shared__ char sm[];
    const int tid = threadIdx.x;
    const int w = tid >> 5;
    const int lane = tid & 31;
    const int qp = lane & 3;
    const int qr = lane >> 2;
    const int bid = blockIdx.x;

    float* b1s = (float*)(sm + OFF_B1);
    float* b2s = (float*)(sm + OFF_B2);
    float* w3s = (float*)(sm + OFF_W3);
    for (int i = tid; i < F1; i += 256) b1s[i] = b1[i];
    if (tid < F2) { b2s[tid] = b2[tid]; w3s[tid] = w3[tid]; }

    {
        const uint4* sp = (const uint4*)(g_a + (size_t)bid * (Tdim * Hdim));
        for (int i = tid; i < 1024; i += 256) {
            int r = i >> 3, c = i & 7;
            *(uint4*)(sm + OFF_A1 + r * (SA1 * 2) + c * 16) = sp[i];
        }
    }
    __syncthreads();

    const int arow = w * 16 + ((lane >> 3) & 1) * 8 + (lane & 7);
    const int acol = ((lane >> 4) & 1) * 8;
    const uint32_t uA1 = smem_u32(sm + OFF_A1) + (arow * SA1 + acol) * 2;
    const uint32_t uW1x4 = smem_u32(sm + OFF_W1) + ((lane & 7) * SW1 + (lane >> 3) * 8) * 2;
    const uint32_t uW2x4 = smem_u32(sm + OFF_W2) +
        ((((lane >> 4) * 8 + (lane & 7)) * SW2) + ((lane >> 3) & 1) * 8) * 2;

    uint32_t Ah[4][4];
#pragma unroll
    for (int kk = 0; kk < 4; kk++) ldsm_x4(Ah[kk], uA1 + kk * 32);

    float D2[16][4];
#pragma unroll
    for (int jj = 0; jj < 16; jj++)
#pragma unroll
        for (int p = 0; p < 4; p++) D2[jj][p] = 0.0f;

    for (int ch = 0; ch < 4; ch++) {
        __syncthreads();
        {
            const uint4* s0 = (const uint4*)(g_w1h + ch * 128 * Hdim);
            for (int i = tid; i < 1024; i += 256) {
                int r = i >> 3, c = i & 7;
                *(uint4*)(sm + OFF_W1 + r * (SW1 * 2) + c * 16) = s0[i];
            }
        }
        {
            for (int i = tid; i < 2048; i += 256) {
                int r = i >> 4, c = i & 15;
                *(uint4*)(sm + OFF_W2 + r * (SW2 * 2) + c * 16) =
                    *(const uint4*)(g_w2h + r * F1 + ch * 128 + c * 8);
            }
        }
        __syncthreads();

#pragma unroll 1
        for (int s = 0; s < 8; s++) {
            float D1[2][4];
#pragma unroll
            for (int jj = 0; jj < 2; jj++) {
#pragma unroll
                for (int p = 0; p < 4; p++) D1[jj][p] = 0.0f;
                const int jn = 2 * s + jj;
                const uint32_t bb = uW1x4 + jn * 8 * SW1 * 2;
                uint32_t bf[8];
                ldsm_x4(bf, bb);
                ldsm_x4(bf + 4, bb + 64);
#pragma unroll
                for (int kk = 0; kk < 4; kk++) mma_fp16(D1[jj], Ah[kk], bf + 2 * kk);
            }
            uint32_t ahf[4];
#pragma unroll
            for (int jj = 0; jj < 2; jj++) {
                const int nb = ch * 128 + (2 * s + jj) * 8 + 2 * qp;
                const float bb0 = b1s[nb], bb1 = b1s[nb + 1];
#pragma unroll
                for (int pp = 0; pp < 2; pp++) {
                    float v0 = fmaxf(D1[jj][2 * pp] + bb0, 0.0f);
                    float v1 = fmaxf(D1[jj][2 * pp + 1] + bb1, 0.0f);
                    ahf[jj * 2 + pp] = hpack(v0, v1);
                }
            }
#pragma unroll
            for (int j2 = 0; j2 < 16; j2 += 2) {
                uint32_t bf[4];
                ldsm_x4(bf, uW2x4 + j2 * 8 * SW2 * 2 + s * 32);
                mma_fp16(D2[j2], ahf, bf);
                mma_fp16(D2[j2 + 1], ahf, bf + 2);
            }
        }
    }

    float s0 = 0.0f, s1 = 0.0f;
#pragma unroll
    for (int j2 = 0; j2 < 16; j2++) {
        const int n2 = j2 * 8 + 2 * qp;
        const float w30 = w3s[n2], w31 = w3s[n2 + 1];
        const float bb0 = b2s[n2], bb1 = b2s[n2 + 1];
        s0 = fmaf(fmaxf(D2[j2][0] + bb0, 0.0f), w30, s0);
        s0 = fmaf(fmaxf(D2[j2][1] + bb1, 0.0f), w31, s0);
        s1 = fmaf(fmaxf(D2[j2][2] + bb0, 0.0f), w30, s1);
        s1 = fmaf(fmaxf(D2[j2][3] + bb1, 0.0f), w31, s1);
    }
    s0 += __shfl_xor_sync(0xffffffffu, s0, 1);
    s0 += __shfl_xor_sync(0xffffffffu, s0, 2);
    s1 += __shfl_xor_sync(0xffffffffu, s1, 1);
    s1 += __shfl_xor_sync(0xffffffffu, s1, 2);
    if (qp == 0) {
        const float bb = b3[0];
        const int m = w * 16 + qr;
        out[bid * 128 + m] = s0 + bb;
        out[bid * 128 + m + 8] = s1 + bb;
    }
}

// ---------------- launch ----------------
extern "C" void kernel_launch(void* const* d_in, const int* in_sizes, int n_in,
                              void* d_out, int out_size) {
    const float* x    = (const float*)d_in[0];
    const float* W_ih = (const float*)d_in[1];
    const float* W_hh = (const float*)d_in[2];
    const float* b_ih = (const float*)d_in[3];
    const float* b_hh = (const float*)d_in[4];
    const float* w1   = (const float*)d_in[5];
    const float* b1   = (const float*)d_in[6];
    const float* w2   = (const float*)d_in[7];
    const float* b2   = (const float*)d_in[8];
    const float* w3   = (const float*)d_in[9];
    const float* b3   = (const float*)d_in[10];
    float* out = (float*)d_out;

    prep_kernel<<<256, 256>>>(w1, w2);

    static int attr_set = 0;
    if (!attr_set) {
        cudaFuncSetAttribute(gru_kernel, cudaFuncAttributeMaxDynamicSharedMemorySize, GSM_TOTAL);
        cudaFuncSetAttribute(mlp_kernel, cudaFuncAttributeMaxDynamicSharedMemorySize, SM_TOTAL);
        attr_set = 1;
    }
    gru_kernel<<<Zdim, 256, GSM_TOTAL>>>(x, W_ih, W_hh, b_ih, b_hh);
    mlp_kernel<<<ZB, 256, SM_TOTAL>>>(b1, b2, b3, w3, out);
}

// round 8
// speedup vs baseline: 8.1455x; 1.0089x over previous
#include <cuda_runtime.h>
#include <cuda_fp16.h>
#include <cstdint>

#define Bdim 32
#define Tdim 128
#define Zdim 100
#define Sdim 6
#define Hdim 64
#define F1 512
#define F2 128
#define ZB (Zdim * Bdim)          // 3200 sequences
#define NROWS (ZB * Tdim)         // 409600

// ---------------- device scratch ----------------
__device__ __align__(16) __half g_a[NROWS * Hdim];   // GRU outputs fp16, row-major tiles
__device__ __align__(16) __half g_w1h[F1 * Hdim];    // w1 [512][64] fp16
__device__ __align__(16) __half g_w2h[F2 * F1];      // w2 [128][512] fp16

// ---------------- helpers ----------------
__device__ __forceinline__ float sigmoid_fast(float v) {
    return __fdividef(1.0f, 1.0f + __expf(-v));
}
__device__ __forceinline__ float tanh_fast(float v) {
    float e = __expf(2.0f * v);
    return 1.0f - __fdividef(2.0f, e + 1.0f);
}
__device__ __forceinline__ uint32_t smem_u32(const void* p) {
    uint32_t a;
    asm("{ .reg .u64 t; cvta.to.shared.u64 t, %1; cvt.u32.u64 %0, t; }" : "=r"(a) : "l"(p));
    return a;
}
__device__ __forceinline__ void ldsm_x4(uint32_t* r, uint32_t addr) {
    asm volatile("ldmatrix.sync.aligned.m8n8.x4.shared.b16 {%0,%1,%2,%3}, [%4];"
                 : "=r"(r[0]), "=r"(r[1]), "=r"(r[2]), "=r"(r[3]) : "r"(addr));
}
__device__ __forceinline__ void ldsm_x2(uint32_t* r, uint32_t addr) {
    asm volatile("ldmatrix.sync.aligned.m8n8.x2.shared.b16 {%0,%1}, [%2];"
                 : "=r"(r[0]), "=r"(r[1]) : "r"(addr));
}
__device__ __forceinline__ void mma_fp16(float* d, const uint32_t* a, const uint32_t* b) {
    asm volatile("mma.sync.aligned.m16n8k16.row.col.f32.f16.f16.f32 "
                 "{%0,%1,%2,%3}, {%4,%5,%6,%7}, {%8,%9}, {%0,%1,%2,%3};"
                 : "+f"(d[0]), "+f"(d[1]), "+f"(d[2]), "+f"(d[3])
                 : "r"(a[0]), "r"(a[1]), "r"(a[2]), "r"(a[3]), "r"(b[0]), "r"(b[1]));
}
__device__ __forceinline__ uint32_t hpack(float x, float y) {
    __half2 t = __floats2half2_rn(x, y);
    return *(uint32_t*)&t;
}
__device__ __forceinline__ uint32_t hpackh(__half x, __half y) {
    return (uint32_t)*(unsigned short*)&x | ((uint32_t)*(unsigned short*)&y << 16);
}

// ---------------- tensor-core GRU (+ inlined weight prep) ----------------
// CTA = one zone = 32 sequences. h in smem fp32; A = h hi/lo fp16;
// lo-correction MMAs applied ONLY to the n-gate (first-order path).
#define GOFF_H    0                      // float h[32][66]           8448 B
#define GOFF_WHH  8448                   // half  whh[192][72]       27648 B
#define GOFF_WIH  36096                  // half  wih[192][24]        9216 B
#define GOFF_AH   45312                  // half  ah[32][72]          4608 B
#define GOFF_AL   49920                  // half  al[32][72]          4608 B
#define GOFF_XA   54528                  // half  xa[2][32][24]       3072 B
#define GSM_TOTAL 57600

__global__ __launch_bounds__(256, 1) void gru_kernel(
    const float* __restrict__ x,
    const float* __restrict__ Wih,
    const float* __restrict__ Whh,
    const float* __restrict__ bihp,
    const float* __restrict__ bhhp,
    const float* __restrict__ w1,
    const float* __restrict__ w2)
{
    extern __shared__ char gsm[];
    float* h_sh  = (float*)(gsm + GOFF_H);
    __half* whh_s = (__half*)(gsm + GOFF_WHH);
    __half* wih_s = (__half*)(gsm + GOFF_WIH);
    __half* ah_s  = (__half*)(gsm + GOFF_AH);
    __half* al_s  = (__half*)(gsm + GOFF_AL);
    __half* xa_s  = (__half*)(gsm + GOFF_XA);

    const int tid = threadIdx.x;
    const int w = tid >> 5;
    const int lane = tid & 31;
    const int qp = lane & 3;
    const int qr = lane >> 2;
    const int zz = blockIdx.x;           // zone
    const int nseq0 = zz * 32;

    // ---- inlined weight prep for the MLP (grid-stride over 100 CTAs) ----
    {
        const int stride = gridDim.x * blockDim.x;
        for (int i = blockIdx.x * blockDim.x + tid; i < F1 * Hdim; i += stride)
            g_w1h[i] = __float2half(w1[i]);
        for (int i = blockIdx.x * blockDim.x + tid; i < F2 * F1; i += stride)
            g_w2h[i] = __float2half(w2[i]);
    }

    // ---- zero h, wih pad, ah/al/xa ----
    for (int i = tid; i < 2112; i += 256) ((float*)(gsm + GOFF_H))[i] = 0.0f;
    for (int i = tid; i < 2304; i += 256) ((uint32_t*)(gsm + GOFF_WIH))[i] = 0u;
    for (int i = tid; i < 3072; i += 256) ((uint32_t*)(gsm + GOFF_AH))[i] = 0u;

    // ---- stage W_hh [192][64] -> fp16 stride 72 ----
    for (int i = tid; i < 192 * 64; i += 256)
        whh_s[(i >> 6) * 72 + (i & 63)] = __float2half(Whh[i]);
    __syncthreads();   // wih zero before writing data cols
    // ---- stage W_ih [192][6] -> fp16 stride 24 (cols 6..23 zero) ----
    for (int i = tid; i < 192 * 6; i += 256)
        wih_s[(i / 6) * 24 + (i % 6)] = __float2half(Wih[i]);
    // ---- stage x(t=0) into xa[0] ----
    const int q = tid / 6, s = tid - (tid / 6) * 6;   // valid for tid<192
    if (tid < 192)
        xa_s[q * 24 + s] = __float2half(x[((q * Tdim + 0) * Zdim + zz) * Sdim + s]);
    __syncthreads();

    // ---- register-resident B fragments ----
    const uint32_t uWhh = smem_u32(whh_s);
    const uint32_t uWih = smem_u32(wih_s);
    const int Lb = lane & 15;
    uint32_t Bhh[3][4][2], Bih[3][2];
#pragma unroll
    for (int g = 0; g < 3; g++) {
        const int ng = g * 64 + w * 8;
        uint32_t r4[4];
        ldsm_x4(r4, uWhh + (uint32_t)(ng + (lane & 7)) * 144 + (uint32_t)(lane >> 3) * 16);
        Bhh[g][0][0] = r4[0]; Bhh[g][0][1] = r4[1];
        Bhh[g][1][0] = r4[2]; Bhh[g][1][1] = r4[3];
        ldsm_x4(r4, uWhh + (uint32_t)(ng + (lane & 7)) * 144 + (uint32_t)(lane >> 3) * 16 + 64);
        Bhh[g][2][0] = r4[0]; Bhh[g][2][1] = r4[1];
        Bhh[g][3][0] = r4[2]; Bhh[g][3][1] = r4[3];
        ldsm_x2(Bih[g], uWih + (uint32_t)(ng + (Lb & 7)) * 48 + (uint32_t)(Lb >> 3) * 16);
    }

    // ---- per-lane biases ----
    const int cb = w * 8 + 2 * qp;       // h-col base for this lane
    const float brz0 = bihp[cb]       + bhhp[cb];
    const float brz1 = bihp[cb + 1]   + bhhp[cb + 1];
    const float bz0  = bihp[64 + cb]  + bhhp[64 + cb];
    const float bz1  = bihp[64 + cb + 1] + bhhp[64 + cb + 1];
    const float bin0 = bihp[128 + cb],     bin1 = bihp[128 + cb + 1];
    const float bhn0 = bhhp[128 + cb],     bhn1 = bhhp[128 + cb + 1];

    // ---- per-lane ldmatrix A addressing ----
    const int arow_lo = ((lane >> 3) & 1) * 8 + (lane & 7);
    const uint32_t acolb = (uint32_t)((lane >> 4) & 1) * 16;
    const uint32_t uAH = smem_u32(ah_s);
    const uint32_t uAL = smem_u32(al_s);
    const uint32_t uXA = smem_u32(xa_s);

    for (int t = 0; t < Tdim; t++) {
        const int cur = t & 1;

        // ---- ldsm A fragments (h hi/lo, x) ----
        uint32_t Ahi[2][4][4], Alo[2][4][4], Ax[2][4];
#pragma unroll
        for (int mt = 0; mt < 2; mt++) {
            const uint32_t rb = (uint32_t)(mt * 16 + arow_lo);
#pragma unroll
            for (int kk = 0; kk < 4; kk++) {
                ldsm_x4(Ahi[mt][kk], uAH + rb * 144 + acolb + kk * 32);
                ldsm_x4(Alo[mt][kk], uAL + rb * 144 + acolb + kk * 32);
            }
            ldsm_x4(Ax[mt], uXA + (uint32_t)cur * 1536 + rb * 48 + acolb);
        }
        // prefetch x(t+1)
        float xvn = 0.0f;
        if (tid < 192 && t + 1 < Tdim)
            xvn = x[((q * Tdim + (t + 1)) * Zdim + zz) * Sdim + s];
        __syncthreads();   // all ldsm reads done before epilogue writes

#pragma unroll
        for (int mt = 0; mt < 2; mt++) {
            float Dh[3][4], Dg[3][4];
#pragma unroll
            for (int g = 0; g < 3; g++) {
#pragma unroll
                for (int p = 0; p < 4; p++) { Dh[g][p] = 0.0f; Dg[g][p] = 0.0f; }
#pragma unroll
                for (int kk = 0; kk < 4; kk++) mma_fp16(Dh[g], Ahi[mt][kk], Bhh[g][kk]);
                mma_fp16(Dg[g], Ax[mt], Bih[g]);
            }
            // lo-correction only for n-gate (g=2)
#pragma unroll
            for (int kk = 0; kk < 4; kk++) mma_fp16(Dh[2], Alo[mt][kk], Bhh[2][kk]);

            // ---- epilogue: gates + h update ----
#pragma unroll
            for (int rr = 0; rr < 2; rr++) {
                const int seqr = mt * 16 + rr * 8 + qr;
                const int i0 = rr * 2, i1 = rr * 2 + 1;
                float r0 = sigmoid_fast(Dg[0][i0] + Dh[0][i0] + brz0);
                float r1 = sigmoid_fast(Dg[0][i1] + Dh[0][i1] + brz1);
                float z0 = sigmoid_fast(Dg[1][i0] + Dh[1][i0] + bz0);
                float z1 = sigmoid_fast(Dg[1][i1] + Dh[1][i1] + bz1);
                float nn0 = tanh_fast(Dg[2][i0] + bin0 + r0 * (Dh[2][i0] + bhn0));
                float nn1 = tanh_fast(Dg[2][i1] + bin1 + r1 * (Dh[2][i1] + bhn1));
                float h0 = h_sh[seqr * 66 + cb];
                float h1 = h_sh[seqr * 66 + cb + 1];
                float hn0 = nn0 + z0 * (h0 - nn0);
                float hn1 = nn1 + z1 * (h1 - nn1);
                h_sh[seqr * 66 + cb]     = hn0;
                h_sh[seqr * 66 + cb + 1] = hn1;
                __half hi0 = __float2half(hn0), hi1 = __float2half(hn1);
                __half lo0 = __float2half(hn0 - __half2float(hi0));
                __half lo1 = __float2half(hn1 - __half2float(hi1));
                *(uint32_t*)&ah_s[seqr * 72 + cb] = hpackh(hi0, hi1);
                *(uint32_t*)&al_s[seqr * 72 + cb] = hpackh(lo0, lo1);
                *(uint32_t*)&g_a[(size_t)(nseq0 + seqr) * (Tdim * Hdim) + t * Hdim + cb]
                    = hpackh(hi0, hi1);
            }
        }
        // store x(t+1) into alternate buffer
        if (tid < 192 && t + 1 < Tdim)
            xa_s[(cur ^ 1) * 768 + q * 24 + s] = __float2half(xvn);
        __syncthreads();
    }
}

// ---------------- tensor-core fused MLP: 512 threads, 2 tiles/CTA ----------------
#define SA1 72
#define SW1 72
#define SW2 136
#define OFF_A1 0                 // 2 tiles x 18432
#define OFF_W1 36864
#define OFF_W2 55296
#define OFF_B1 90112
#define OFF_B2 92160
#define OFF_W3 92672
#define SM_TOTAL 93184

__global__ __launch_bounds__(512, 1) void mlp_kernel(
    const float* __restrict__ b1,
    const float* __restrict__ b2,
    const float* __restrict__ b3,
    const float* __restrict__ w3,
    float* __restrict__ out)
{
    extern __shared__ char sm[];
    const int tid = threadIdx.x;
    const int w = tid >> 5;          // 0..15
    const int wg = w >> 3;           // tile group 0/1
    const int wl = w & 7;            // warp within group
    const int lane = tid & 31;
    const int qp = lane & 3;
    const int qr = lane >> 2;
    const int bid = blockIdx.x;
    const int tile = bid * 2 + wg;   // sequence tile for this warp group

    float* b1s = (float*)(sm + OFF_B1);
    float* b2s = (float*)(sm + OFF_B2);
    float* w3s = (float*)(sm + OFF_W3);
    for (int i = tid; i < F1; i += 512) b1s[i] = b1[i];
    if (tid < F2) { b2s[tid] = b2[tid]; w3s[tid] = w3[tid]; }

    // ---- stage two A1 tiles ----
    {
        for (int i = tid; i < 2048; i += 512) {
            int tt = i >> 10, idx = i & 1023;
            int r = idx >> 3, c = idx & 7;
            *(uint4*)(sm + OFF_A1 + tt * 18432 + r * (SA1 * 2) + c * 16) =
                ((const uint4*)(g_a + (size_t)(bid * 2 + tt) * (Tdim * Hdim)))[idx];
        }
    }
    __syncthreads();

    const int arow = wl * 16 + ((lane >> 3) & 1) * 8 + (lane & 7);
    const int acol = ((lane >> 4) & 1) * 8;
    const uint32_t uA1 = smem_u32(sm + OFF_A1 + wg * 18432) + (arow * SA1 + acol) * 2;
    const uint32_t uW1x4 = smem_u32(sm + OFF_W1) + ((lane & 7) * SW1 + (lane >> 3) * 8) * 2;
    const uint32_t uW2x4 = smem_u32(sm + OFF_W2) +
        ((((lane >> 4) * 8 + (lane & 7)) * SW2) + ((lane >> 3) & 1) * 8) * 2;

    uint32_t Ah[4][4];
#pragma unroll
    for (int kk = 0; kk < 4; kk++) ldsm_x4(Ah[kk], uA1 + kk * 32);

    float D2[16][4];
#pragma unroll
    for (int jj = 0; jj < 16; jj++)
#pragma unroll
        for (int p = 0; p < 4; p++) D2[jj][p] = 0.0f;

    for (int ch = 0; ch < 4; ch++) {
        __syncthreads();
        {
            const uint4* s0 = (const uint4*)(g_w1h + ch * 128 * Hdim);
            for (int i = tid; i < 1024; i += 512) {
                int r = i >> 3, c = i & 7;
                *(uint4*)(sm + OFF_W1 + r * (SW1 * 2) + c * 16) = s0[i];
            }
        }
        {
            for (int i = tid; i < 2048; i += 512) {
                int r = i >> 4, c = i & 15;
                *(uint4*)(sm + OFF_W2 + r * (SW2 * 2) + c * 16) =
                    *(const uint4*)(g_w2h + r * F1 + ch * 128 + c * 8);
            }
        }
        __syncthreads();

#pragma unroll 1
        for (int s = 0; s < 8; s++) {
            float D1[2][4];
#pragma unroll
            for (int jj = 0; jj < 2; jj++) {
#pragma unroll
                for (int p = 0; p < 4; p++) D1[jj][p] = 0.0f;
                const int jn = 2 * s + jj;
                const uint32_t bb = uW1x4 + jn * 8 * SW1 * 2;
                uint32_t bf[8];
                ldsm_x4(bf, bb);
                ldsm_x4(bf + 4, bb + 64);
#pragma unroll
                for (int kk = 0; kk < 4; kk++) mma_fp16(D1[jj], Ah[kk], bf + 2 * kk);
            }
            uint32_t ahf[4];
#pragma unroll
            for (int jj = 0; jj < 2; jj++) {
                const int nb = ch * 128 + (2 * s + jj) * 8 + 2 * qp;
                const float bb0 = b1s[nb], bb1 = b1s[nb + 1];
#pragma unroll
                for (int pp = 0; pp < 2; pp++) {
                    float v0 = fmaxf(D1[jj][2 * pp] + bb0, 0.0f);
                    float v1 = fmaxf(D1[jj][2 * pp + 1] + bb1, 0.0f);
                    ahf[jj * 2 + pp] = hpack(v0, v1);
                }
            }
#pragma unroll
            for (int j2 = 0; j2 < 16; j2 += 2) {
                uint32_t bf[4];
                ldsm_x4(bf, uW2x4 + j2 * 8 * SW2 * 2 + s * 32);
                mma_fp16(D2[j2], ahf, bf);
                mma_fp16(D2[j2 + 1], ahf, bf + 2);
            }
        }
    }

    float s0 = 0.0f, s1 = 0.0f;
#pragma unroll
    for (int j2 = 0; j2 < 16; j2++) {
        const int n2 = j2 * 8 + 2 * qp;
        const float w30 = w3s[n2], w31 = w3s[n2 + 1];
        const float bb0 = b2s[n2], bb1 = b2s[n2 + 1];
        s0 = fmaf(fmaxf(D2[j2][0] + bb0, 0.0f), w30, s0);
        s0 = fmaf(fmaxf(D2[j2][1] + bb1, 0.0f), w31, s0);
        s1 = fmaf(fmaxf(D2[j2][2] + bb0, 0.0f), w30, s1);
        s1 = fmaf(fmaxf(D2[j2][3] + bb1, 0.0f), w31, s1);
    }
    s0 += __shfl_xor_sync(0xffffffffu, s0, 1);
    s0 += __shfl_xor_sync(0xffffffffu, s0, 2);
    s1 += __shfl_xor_sync(0xffffffffu, s1, 1);
    s1 += __shfl_xor_sync(0xffffffffu, s1, 2);
    if (qp == 0) {
        const float bb = b3[0];
        const int m = wl * 16 + qr;
        out[tile * 128 + m] = s0 + bb;
        out[tile * 128 + m + 8] = s1 + bb;
    }
}

// ---------------- launch ----------------
extern "C" void kernel_launch(void* const* d_in, const int* in_sizes, int n_in,
                              void* d_out, int out_size) {
    const float* x    = (const float*)d_in[0];
    const float* W_ih = (const float*)d_in[1];
    const float* W_hh = (const float*)d_in[2];
    const float* b_ih = (const float*)d_in[3];
    const float* b_hh = (const float*)d_in[4];
    const float* w1   = (const float*)d_in[5];
    const float* b1   = (const float*)d_in[6];
    const float* w2   = (const float*)d_in[7];
    const float* b2   = (const float*)d_in[8];
    const float* w3   = (const float*)d_in[9];
    const float* b3   = (const float*)d_in[10];
    float* out = (float*)d_out;

    static int attr_set = 0;
    if (!attr_set) {
        cudaFuncSetAttribute(gru_kernel, cudaFuncAttributeMaxDynamicSharedMemorySize, GSM_TOTAL);
        cudaFuncSetAttribute(mlp_kernel, cudaFuncAttributeMaxDynamicSharedMemorySize, SM_TOTAL);
        attr_set = 1;
    }
    gru_kernel<<<Zdim, 256, GSM_TOTAL>>>(x, W_ih, W_hh, b_ih, b_hh, w1, w2);
    mlp_kernel<<<ZB / 2, 512, SM_TOTAL>>>(b1, b2, b3, w3, out);
}